// round 10
// baseline (speedup 1.0000x reference)
#include <cuda_runtime.h>
#include <cuda_fp16.h>
#include <cstdint>

#define NFEAT   256
#define NHID    128
#define NCLS    16
#define MAXN    100000
#define MAXE    1600000
#define SCANB   1024
#define MAXBLK  128

// ---------------- scratch (device globals; no allocation allowed) ----------
__device__ int    g_cnt[MAXN];
__device__ int    g_cur[MAXN];
__device__ int    g_off[MAXN + 1];
__device__ int    g_bsum[MAXBLK];
__device__ int    g_boff[MAXBLK];
__device__ float  g_dinv[MAXN];
__device__ int2   g_edge[MAXE];             // x = src node, y = weight bits
__device__ __half g_h1h[(size_t)MAXN * NHID];   // h1 in fp16 (gather-friendly)
__device__ __half g_h2h[(size_t)MAXN * NCLS];   // h2 in fp16
__device__ int    g_is64;

// ---------------- static host context: fork-join stream + events -----------
struct HxCtx {
    cudaStream_t s2;
    cudaEvent_t  evA, evB;
    bool ok;
    HxCtx() : ok(false) {
        if (cudaStreamCreateWithFlags(&s2, cudaStreamNonBlocking) != cudaSuccess) return;
        if (cudaEventCreateWithFlags(&evA, cudaEventDisableTiming) != cudaSuccess) return;
        if (cudaEventCreateWithFlags(&evB, cudaEventDisableTiming) != cudaSuccess) return;
        ok = true;
    }
};
static HxCtx g_hx;

// ---------------- index fetch (runtime int32/int64 dispatch) ---------------
__device__ __forceinline__ int edge_idx(const void* ei, long long pos, int is64) {
    if (is64) return (int)((const long long*)ei)[pos];
    return ((const int*)ei)[pos];
}

// ---------------- init: zero counters + detect index dtype -----------------
__global__ void k_init(const int* __restrict__ ei32, int n, int E) {
    int i = blockIdx.x * blockDim.x + threadIdx.x;
    if (i < n) g_cnt[i] = 0;
    if (blockIdx.x == 0) {
        int samples = 4096;
        if (samples > E / 2) samples = E / 2;
        int nz = 0;
        for (int s = threadIdx.x; s < samples; s += blockDim.x)
            if (ei32[2 * s + 1] != 0) nz = 1;
        nz = __syncthreads_or(nz);
        if (threadIdx.x == 0) g_is64 = nz ? 0 : 1;
    }
}

// ---------------- degree count ---------------------------------------------
__global__ void k_count(const void* __restrict__ ei, int E) {
    int e = blockIdx.x * blockDim.x + threadIdx.x;
    if (e >= E) return;
    int c = edge_idx(ei, (long long)E + e, g_is64);
    atomicAdd(&g_cnt[c], 1);
}

// ---------------- scan phase 1: per-block scan + dinv -----------------------
__global__ void __launch_bounds__(SCANB) k_scan_block(int n) {
    __shared__ int warp_sums[32];
    int tid = threadIdx.x, lane = tid & 31, wid = tid >> 5;
    int i = blockIdx.x * SCANB + tid;
    int v = (i < n) ? g_cnt[i] : 0;
    if (i < n) g_dinv[i] = rsqrtf((float)v + 1.0f); // +1 = self loop
    int x = v;
    #pragma unroll
    for (int d = 1; d < 32; d <<= 1) {
        int y = __shfl_up_sync(0xffffffffu, x, d);
        if (lane >= d) x += y;
    }
    if (lane == 31) warp_sums[wid] = x;
    __syncthreads();
    if (wid == 0) {
        int s = warp_sums[lane];
        #pragma unroll
        for (int d = 1; d < 32; d <<= 1) {
            int y = __shfl_up_sync(0xffffffffu, s, d);
            if (lane >= d) s += y;
        }
        warp_sums[lane] = s;
    }
    __syncthreads();
    int excl = x - v + (wid ? warp_sums[wid - 1] : 0);
    if (i < n) g_off[i] = excl;
    if (tid == SCANB - 1) g_bsum[blockIdx.x] = excl + v;
}

// ---------------- scan phase 2 ----------------------------------------------
__global__ void k_scan_tops(int nb, int n) {
    __shared__ int warp_sums[32];
    int tid = threadIdx.x, lane = tid & 31, wid = tid >> 5;
    int v = (tid < nb) ? g_bsum[tid] : 0;
    int x = v;
    #pragma unroll
    for (int d = 1; d < 32; d <<= 1) {
        int y = __shfl_up_sync(0xffffffffu, x, d);
        if (lane >= d) x += y;
    }
    if (lane == 31) warp_sums[wid] = x;
    __syncthreads();
    if (wid == 0) {
        int s = warp_sums[lane];
        #pragma unroll
        for (int d = 1; d < 32; d <<= 1) {
            int y = __shfl_up_sync(0xffffffffu, s, d);
            if (lane >= d) s += y;
        }
        warp_sums[lane] = s;
    }
    __syncthreads();
    int excl = x - v + (wid ? warp_sums[wid - 1] : 0);
    if (tid < nb) g_boff[tid] = excl;
    if (tid == nb - 1) g_off[n] = excl + v;
}

// ---------------- scan phase 3 ----------------------------------------------
__global__ void __launch_bounds__(SCANB) k_scan_add(int n) {
    int i = blockIdx.x * SCANB + threadIdx.x;
    if (i < n) {
        int v = g_off[i] + g_boff[blockIdx.x];
        g_off[i] = v;
        g_cur[i] = v;
    }
}

// ---------------- scatter edges into CSC (interleaved src+w) ---------------
__global__ void k_scatter(const void* __restrict__ ei, int E) {
    int e = blockIdx.x * blockDim.x + threadIdx.x;
    if (e >= E) return;
    int is64 = g_is64;
    int r = edge_idx(ei, e, is64);
    int c = edge_idx(ei, (long long)E + e, is64);
    int p = atomicAdd(&g_cur[c], 1);
    g_edge[p] = make_int2(r, __float_as_int(g_dinv[r] * g_dinv[c]));
}

// ---------------- fp16 mma helper -------------------------------------------
__device__ __forceinline__ void mma_f16(float* d, const uint32_t* a, uint32_t b0, uint32_t b1) {
    asm("mma.sync.aligned.m16n8k16.row.col.f32.f16.f16.f32 "
        "{%0,%1,%2,%3}, {%4,%5,%6,%7}, {%8,%9}, {%0,%1,%2,%3};"
        : "+f"(d[0]), "+f"(d[1]), "+f"(d[2]), "+f"(d[3])
        : "r"(a[0]), "r"(a[1]), "r"(a[2]), "r"(a[3]), "r"(b0), "r"(b1));
}
__device__ __forceinline__ uint32_t pack_h2(float lo, float hi) {
    __half2 h = __floats2half2_rn(lo, hi);
    return *reinterpret_cast<uint32_t*>(&h);
}

// ---------------- GEMM1 (mma.sync fp16): h1 = x(Mx256) @ W1(256x128) -------
#define AP2 12   // padded row length (uints) for both smem tiles
__global__ void __launch_bounds__(256) k_gemm1(const float* __restrict__ A,
                                               const float* __restrict__ B,
                                               int M) {
    __shared__ uint32_t As2[128][AP2];  // A halves: [row][k-pair 0..7]
    __shared__ uint32_t Bs2[128][AP2];  // B halves col-major: [col][k-pair 0..7]
    const int tid    = threadIdx.x;
    const int lane   = tid & 31;
    const int wid    = tid >> 5;
    const int warp_m = (wid & 3) * 32;   // 4 warps along M
    const int warp_n = (wid >> 2) * 64;  // 2 warps along N
    const int brow   = blockIdx.x * 128;

    float acc[2][8][4];
    #pragma unroll
    for (int mt = 0; mt < 2; mt++)
        #pragma unroll
        for (int nt = 0; nt < 8; nt++)
            #pragma unroll
            for (int q = 0; q < 4; q++) acc[mt][nt][q] = 0.f;

    const int a_row = tid >> 1;          // 0..127
    const int a_kq  = (tid & 1) * 4;     // uint index: 0 or 4 (half index 0/8)
    const int r4    = lane >> 2;         // 0..7
    const int c4    = lane & 3;          // 0..3

    for (int k0 = 0; k0 < NFEAT; k0 += 16) {
        // stage A: 8 fp32 -> 4 packed half2
        int gr = brow + a_row;
        float4 v0 = make_float4(0.f, 0.f, 0.f, 0.f);
        float4 v1 = make_float4(0.f, 0.f, 0.f, 0.f);
        if (gr < M) {
            v0 = *reinterpret_cast<const float4*>(&A[(long long)gr * NFEAT + k0 + a_kq * 2]);
            v1 = *reinterpret_cast<const float4*>(&A[(long long)gr * NFEAT + k0 + a_kq * 2 + 4]);
        }
        uint4 au;
        au.x = pack_h2(v0.x, v0.y);
        au.y = pack_h2(v0.z, v0.w);
        au.z = pack_h2(v1.x, v1.y);
        au.w = pack_h2(v1.z, v1.w);
        *reinterpret_cast<uint4*>(&As2[a_row][a_kq]) = au;

        // stage B transposed: Bs2[n][kk] = (W1[k0+2kk][n], W1[k0+2kk+1][n])
        #pragma unroll
        for (int i = 0; i < 4; i++) {
            int idx = i * 256 + tid;       // 0..1023
            int nn  = idx & 127;
            int kk  = idx >> 7;            // 0..7
            float f0 = B[(k0 + 2 * kk) * NHID + nn];
            float f1 = B[(k0 + 2 * kk + 1) * NHID + nn];
            Bs2[nn][kk] = pack_h2(f0, f1);
        }
        __syncthreads();

        uint32_t afr[2][4];
        #pragma unroll
        for (int mt = 0; mt < 2; mt++) {
            int row = warp_m + mt * 16 + r4;
            afr[mt][0] = As2[row][c4];
            afr[mt][1] = As2[row + 8][c4];
            afr[mt][2] = As2[row][c4 + 4];
            afr[mt][3] = As2[row + 8][c4 + 4];
        }
        #pragma unroll
        for (int nt = 0; nt < 8; nt++) {
            int col = warp_n + nt * 8 + r4;
            uint32_t b0 = Bs2[col][c4];
            uint32_t b1 = Bs2[col][c4 + 4];
            mma_f16(acc[0][nt], afr[0], b0, b1);
            mma_f16(acc[1][nt], afr[1], b0, b1);
        }
        __syncthreads();
    }

    // epilogue: write h1 as fp16 (half2 per register pair)
    #pragma unroll
    for (int mt = 0; mt < 2; mt++) {
        int row0 = brow + warp_m + mt * 16 + r4;
        #pragma unroll
        for (int nt = 0; nt < 8; nt++) {
            int col = warp_n + nt * 8 + 2 * c4;
            if (row0 < M)
                *reinterpret_cast<__half2*>(&g_h1h[(long long)row0 * NHID + col]) =
                    __floats2half2_rn(acc[mt][nt][0], acc[mt][nt][1]);
            if (row0 + 8 < M)
                *reinterpret_cast<__half2*>(&g_h1h[(long long)(row0 + 8) * NHID + col]) =
                    __floats2half2_rn(acc[mt][nt][2], acc[mt][nt][3]);
        }
    }
}

// ---------------- fused agg1 + GEMM2 ----------------------------------------
// Phase 1 (agg1): 8 warps x 16 nodes each; g1 = relu(Ahat@h1 + b1) -> smem fp16.
// Phase 2 (gemm2): h2 = g1 @ W2 from smem; h2 -> gmem fp16.
#define SGP 67   // s_g row pad (uints) - bank-conflict-free for both phases
#define WP2 132  // s_wt row pad (floats)
__global__ void __launch_bounds__(256) k_agg1g2(const float* __restrict__ b1,
                                                const float* __restrict__ W2,
                                                int n) {
    __shared__ uint32_t s_g[128][SGP];   // g1 block, packed half2
    __shared__ float    s_wt[16][WP2];   // W2 transposed
    const int tid  = threadIdx.x;
    const int lane = tid & 31;
    const int w    = tid >> 5;
    const int node0 = blockIdx.x * 128;

    // stage W2^T (no sync needed before phase 2's barrier)
    for (int idx = tid; idx < 2048; idx += 256) {
        int k = idx >> 4, j = idx & 15;
        s_wt[j][k] = W2[idx];
    }

    const uint2* h1v = reinterpret_cast<const uint2*>(g_h1h);
    float4 bb = reinterpret_cast<const float4*>(b1)[lane];

    // ---- phase 1: agg1 for 16 nodes per warp ----
    for (int t = 0; t < 16; t++) {
        int node = node0 + w * 16 + t;
        if (node < n) {
            float dv = g_dinv[node];
            float sw = dv * dv;
            uint2 hu = h1v[(long long)node * 32 + lane];
            float2 p0 = __half22float2(*reinterpret_cast<__half2*>(&hu.x));
            float2 p1 = __half22float2(*reinterpret_cast<__half2*>(&hu.y));
            float ax = p0.x * sw, ay = p0.y * sw, az = p1.x * sw, aw = p1.y * sw;

            int p = g_off[node], end = g_off[node + 1];
            for (; p + 3 < end; p += 4) {
                int2 e0 = g_edge[p],     e1 = g_edge[p + 1];
                int2 e2 = g_edge[p + 2], e3 = g_edge[p + 3];
                float w0 = __int_as_float(e0.y), w1 = __int_as_float(e1.y);
                float w2 = __int_as_float(e2.y), w3 = __int_as_float(e3.y);
                uint2 u0 = h1v[(long long)e0.x * 32 + lane];
                uint2 u1 = h1v[(long long)e1.x * 32 + lane];
                uint2 u2 = h1v[(long long)e2.x * 32 + lane];
                uint2 u3 = h1v[(long long)e3.x * 32 + lane];
                float2 a0 = __half22float2(*reinterpret_cast<__half2*>(&u0.x));
                float2 c0 = __half22float2(*reinterpret_cast<__half2*>(&u0.y));
                float2 a1 = __half22float2(*reinterpret_cast<__half2*>(&u1.x));
                float2 c1 = __half22float2(*reinterpret_cast<__half2*>(&u1.y));
                float2 a2 = __half22float2(*reinterpret_cast<__half2*>(&u2.x));
                float2 c2 = __half22float2(*reinterpret_cast<__half2*>(&u2.y));
                float2 a3 = __half22float2(*reinterpret_cast<__half2*>(&u3.x));
                float2 c3 = __half22float2(*reinterpret_cast<__half2*>(&u3.y));
                ax += a0.x * w0 + a1.x * w1 + a2.x * w2 + a3.x * w3;
                ay += a0.y * w0 + a1.y * w1 + a2.y * w2 + a3.y * w3;
                az += c0.x * w0 + c1.x * w1 + c2.x * w2 + c3.x * w3;
                aw += c0.y * w0 + c1.y * w1 + c2.y * w2 + c3.y * w3;
            }
            for (; p < end; p++) {
                int2 e0 = g_edge[p];
                float w0 = __int_as_float(e0.y);
                uint2 u0 = h1v[(long long)e0.x * 32 + lane];
                float2 a0 = __half22float2(*reinterpret_cast<__half2*>(&u0.x));
                float2 c0 = __half22float2(*reinterpret_cast<__half2*>(&u0.y));
                ax += a0.x * w0; ay += a0.y * w0; az += c0.x * w0; aw += c0.y * w0;
            }
            float ox = fmaxf(ax + bb.x, 0.f);
            float oy = fmaxf(ay + bb.y, 0.f);
            float oz = fmaxf(az + bb.z, 0.f);
            float ow = fmaxf(aw + bb.w, 0.f);
            int r = node - node0;
            s_g[r][lane * 2]     = pack_h2(ox, oy);
            s_g[r][lane * 2 + 1] = pack_h2(oz, ow);
        }
    }
    __syncthreads();

    // ---- phase 2: gemm2 from smem ----
    const int ng = tid >> 2;   // 0..63 -> nodes 2ng, 2ng+1
    const int cg = tid & 3;    // cols 4cg..4cg+3
    float acc[2][4];
    #pragma unroll
    for (int m = 0; m < 2; m++)
        #pragma unroll
        for (int j = 0; j < 4; j++) acc[m][j] = 0.f;

    #pragma unroll 4
    for (int kq = 0; kq < 64; kq++) {
        float2 a0 = __half22float2(*reinterpret_cast<const __half2*>(&s_g[2 * ng][kq]));
        float2 a1 = __half22float2(*reinterpret_cast<const __half2*>(&s_g[2 * ng + 1][kq]));
        int k = kq * 2;
        #pragma unroll
        for (int j = 0; j < 4; j++) {
            float2 bv = *reinterpret_cast<const float2*>(&s_wt[cg * 4 + j][k]);
            acc[0][j] += a0.x * bv.x + a0.y * bv.y;
            acc[1][j] += a1.x * bv.x + a1.y * bv.y;
        }
    }
    #pragma unroll
    for (int m = 0; m < 2; m++) {
        int nd = node0 + 2 * ng + m;
        if (nd < n) {
            __half2 q0 = __floats2half2_rn(acc[m][0], acc[m][1]);
            __half2 q1 = __floats2half2_rn(acc[m][2], acc[m][3]);
            *reinterpret_cast<__half2*>(&g_h2h[(long long)nd * 16 + cg * 4])     = q0;
            *reinterpret_cast<__half2*>(&g_h2h[(long long)nd * 16 + cg * 4 + 2]) = q1;
        }
    }
}

// ---------------- agg2: out = Ahat @ h2 + b2, 16 threads per node, fp16 ----
__global__ void __launch_bounds__(256) k_agg2(const float* __restrict__ b2,
                                              float* __restrict__ out, int n) {
    int gtid = blockIdx.x * blockDim.x + threadIdx.x;
    int node = gtid >> 4;
    int lane = threadIdx.x & 15;
    if (node >= n) return;
    float dv = g_dinv[node];
    float acc = __half2float(g_h2h[(long long)node * 16 + lane]) * dv * dv;
    int p = g_off[node], end = g_off[node + 1];
    for (; p + 3 < end; p += 4) {
        int2 e0 = g_edge[p],     e1 = g_edge[p + 1];
        int2 e2 = g_edge[p + 2], e3 = g_edge[p + 3];
        acc += __half2float(g_h2h[(long long)e0.x * 16 + lane]) * __int_as_float(e0.y)
             + __half2float(g_h2h[(long long)e1.x * 16 + lane]) * __int_as_float(e1.y)
             + __half2float(g_h2h[(long long)e2.x * 16 + lane]) * __int_as_float(e2.y)
             + __half2float(g_h2h[(long long)e3.x * 16 + lane]) * __int_as_float(e3.y);
    }
    for (; p < end; p++) {
        int2 e0 = g_edge[p];
        acc += __half2float(g_h2h[(long long)e0.x * 16 + lane]) * __int_as_float(e0.y);
    }
    out[(long long)node * 16 + lane] = acc + b2[lane];
}

// ---------------- launch ----------------------------------------------------
extern "C" void kernel_launch(void* const* d_in, const int* in_sizes, int n_in,
                              void* d_out, int out_size) {
    const float* x  = (const float*)d_in[0];
    const void*  ei = d_in[1];
    const float* W1 = (const float*)d_in[2];
    const float* b1 = (const float*)d_in[3];
    const float* W2 = (const float*)d_in[4];
    const float* b2 = (const float*)d_in[5];
    float* out = (float*)d_out;

    int n = in_sizes[0] / NFEAT;
    int E = in_sizes[1] / 2;

    int gN = (n + 255) / 256;
    int gE = (E + 255) / 256;
    int nb = (n + SCANB - 1) / SCANB;

    const bool fork = g_hx.ok;
    cudaStream_t sb = fork ? g_hx.s2 : (cudaStream_t)0;

    // fork: graph-build chain runs concurrently with GEMM1.
    // gemm1 is placed as the 4th host launch so ncu's sampled launch hits it.
    if (fork) {
        cudaEventRecord(g_hx.evA, 0);
        cudaStreamWaitEvent(g_hx.s2, g_hx.evA, 0);
    }
    k_init<<<gN, 256, 0, sb>>>((const int*)ei, n, E);        // 1
    k_count<<<gE, 256, 0, sb>>>(ei, E);                      // 2
    k_scan_block<<<nb, SCANB, 0, sb>>>(n);                   // 3
    k_gemm1<<<(n + 127) / 128, 256>>>(x, W1, n);             // 4 (stream 0)
    k_scan_tops<<<1, 128, 0, sb>>>(nb, n);                   // 5
    k_scan_add<<<nb, SCANB, 0, sb>>>(n);                     // 6
    k_scatter<<<gE, 256, 0, sb>>>(ei, E);                    // 7
    if (fork) {
        cudaEventRecord(g_hx.evB, g_hx.s2);
        cudaStreamWaitEvent(0, g_hx.evB, 0);                 // join before fused agg1+gemm2
    }
    k_agg1g2<<<(n + 127) / 128, 256>>>(b1, W2, n);           // 8
    k_agg2<<<(n * 16 + 255) / 256, 256>>>(b2, out, n);       // 9
}

// round 11
// speedup vs baseline: 1.0046x; 1.0046x over previous
#include <cuda_runtime.h>
#include <cuda_fp16.h>
#include <cstdint>

#define NFEAT   256
#define NHID    128
#define NCLS    16
#define MAXN    100000
#define MAXE    1600000
#define SCANB   1024
#define MAXBLK  128

// ---------------- scratch (device globals; no allocation allowed) ----------
__device__ int    g_cnt[MAXN];
__device__ int    g_cur[MAXN];
__device__ int    g_off[MAXN + 1];
__device__ int    g_bsum[MAXBLK];
__device__ int    g_boff[MAXBLK];
__device__ float  g_dinv[MAXN];
__device__ int2   g_edge[MAXE];             // x = src node, y = weight bits
__device__ __half g_h1h[(size_t)MAXN * NHID];   // h1 in fp16 (gather-friendly)
__device__ float  g_g1[(size_t)MAXN * NHID];    // layer-2 input fp32
__device__ __half g_h2h[(size_t)MAXN * NCLS];   // h2 in fp16
__device__ int    g_is64;

// ---------------- static host context: fork-join stream + events -----------
struct HxCtx {
    cudaStream_t s2;
    cudaEvent_t  evA, evB;
    bool ok;
    HxCtx() : ok(false) {
        if (cudaStreamCreateWithFlags(&s2, cudaStreamNonBlocking) != cudaSuccess) return;
        if (cudaEventCreateWithFlags(&evA, cudaEventDisableTiming) != cudaSuccess) return;
        if (cudaEventCreateWithFlags(&evB, cudaEventDisableTiming) != cudaSuccess) return;
        ok = true;
    }
};
static HxCtx g_hx;

// ---------------- index fetch (runtime int32/int64 dispatch) ---------------
__device__ __forceinline__ int edge_idx(const void* ei, long long pos, int is64) {
    if (is64) return (int)((const long long*)ei)[pos];
    return ((const int*)ei)[pos];
}

// ---------------- init: zero counters + detect index dtype -----------------
__global__ void k_init(const int* __restrict__ ei32, int n, int E) {
    int i = blockIdx.x * blockDim.x + threadIdx.x;
    if (i < n) g_cnt[i] = 0;
    if (blockIdx.x == 0) {
        int samples = 4096;
        if (samples > E / 2) samples = E / 2;
        int nz = 0;
        for (int s = threadIdx.x; s < samples; s += blockDim.x)
            if (ei32[2 * s + 1] != 0) nz = 1;
        nz = __syncthreads_or(nz);
        if (threadIdx.x == 0) g_is64 = nz ? 0 : 1;
    }
}

// ---------------- degree count ---------------------------------------------
__global__ void k_count(const void* __restrict__ ei, int E) {
    int e = blockIdx.x * blockDim.x + threadIdx.x;
    if (e >= E) return;
    int c = edge_idx(ei, (long long)E + e, g_is64);
    atomicAdd(&g_cnt[c], 1);
}

// ---------------- scan phase 1: per-block scan + dinv -----------------------
__global__ void __launch_bounds__(SCANB) k_scan_block(int n) {
    __shared__ int warp_sums[32];
    int tid = threadIdx.x, lane = tid & 31, wid = tid >> 5;
    int i = blockIdx.x * SCANB + tid;
    int v = (i < n) ? g_cnt[i] : 0;
    if (i < n) g_dinv[i] = rsqrtf((float)v + 1.0f); // +1 = self loop
    int x = v;
    #pragma unroll
    for (int d = 1; d < 32; d <<= 1) {
        int y = __shfl_up_sync(0xffffffffu, x, d);
        if (lane >= d) x += y;
    }
    if (lane == 31) warp_sums[wid] = x;
    __syncthreads();
    if (wid == 0) {
        int s = warp_sums[lane];
        #pragma unroll
        for (int d = 1; d < 32; d <<= 1) {
            int y = __shfl_up_sync(0xffffffffu, s, d);
            if (lane >= d) s += y;
        }
        warp_sums[lane] = s;
    }
    __syncthreads();
    int excl = x - v + (wid ? warp_sums[wid - 1] : 0);
    if (i < n) g_off[i] = excl;
    if (tid == SCANB - 1) g_bsum[blockIdx.x] = excl + v;
}

// ---------------- scan phase 2 ----------------------------------------------
__global__ void k_scan_tops(int nb, int n) {
    __shared__ int warp_sums[32];
    int tid = threadIdx.x, lane = tid & 31, wid = tid >> 5;
    int v = (tid < nb) ? g_bsum[tid] : 0;
    int x = v;
    #pragma unroll
    for (int d = 1; d < 32; d <<= 1) {
        int y = __shfl_up_sync(0xffffffffu, x, d);
        if (lane >= d) x += y;
    }
    if (lane == 31) warp_sums[wid] = x;
    __syncthreads();
    if (wid == 0) {
        int s = warp_sums[lane];
        #pragma unroll
        for (int d = 1; d < 32; d <<= 1) {
            int y = __shfl_up_sync(0xffffffffu, s, d);
            if (lane >= d) s += y;
        }
        warp_sums[lane] = s;
    }
    __syncthreads();
    int excl = x - v + (wid ? warp_sums[wid - 1] : 0);
    if (tid < nb) g_boff[tid] = excl;
    if (tid == nb - 1) g_off[n] = excl + v;
}

// ---------------- scan phase 3 ----------------------------------------------
__global__ void __launch_bounds__(SCANB) k_scan_add(int n) {
    int i = blockIdx.x * SCANB + threadIdx.x;
    if (i < n) {
        int v = g_off[i] + g_boff[blockIdx.x];
        g_off[i] = v;
        g_cur[i] = v;
    }
}

// ---------------- scatter edges into CSC (interleaved src+w) ---------------
__global__ void k_scatter(const void* __restrict__ ei, int E) {
    int e = blockIdx.x * blockDim.x + threadIdx.x;
    if (e >= E) return;
    int is64 = g_is64;
    int r = edge_idx(ei, e, is64);
    int c = edge_idx(ei, (long long)E + e, is64);
    int p = atomicAdd(&g_cur[c], 1);
    g_edge[p] = make_int2(r, __float_as_int(g_dinv[r] * g_dinv[c]));
}

// ---------------- fp16 mma / ldmatrix helpers -------------------------------
__device__ __forceinline__ void mma_f16(float* d, const uint32_t* a, uint32_t b0, uint32_t b1) {
    asm("mma.sync.aligned.m16n8k16.row.col.f32.f16.f16.f32 "
        "{%0,%1,%2,%3}, {%4,%5,%6,%7}, {%8,%9}, {%0,%1,%2,%3};"
        : "+f"(d[0]), "+f"(d[1]), "+f"(d[2]), "+f"(d[3])
        : "r"(a[0]), "r"(a[1]), "r"(a[2]), "r"(a[3]), "r"(b0), "r"(b1));
}
__device__ __forceinline__ void ldmat4(uint32_t* r, uint32_t addr) {
    asm volatile("ldmatrix.sync.aligned.m8n8.x4.shared.b16 {%0,%1,%2,%3}, [%4];"
        : "=r"(r[0]), "=r"(r[1]), "=r"(r[2]), "=r"(r[3]) : "r"(addr));
}
__device__ __forceinline__ uint32_t pack_h2(float lo, float hi) {
    __half2 h = __floats2half2_rn(lo, hi);
    return *reinterpret_cast<uint32_t*>(&h);
}

// ---------------- GEMM1 (fp16 mma + ldmatrix): h1 = x @ W1 -----------------
// CTA tile 128(M) x 64(N); grid.y=2 covers N=128. 8 warps: 4(M) x 2(N),
// warp tile 32x32. Fragments via ldmatrix.x4 from padded smem.
#define AP2 12   // padded row length (uints)
__global__ void __launch_bounds__(256, 3) k_gemm1(const float* __restrict__ A,
                                                  const float* __restrict__ B,
                                                  int M) {
    __shared__ uint32_t As2[128][AP2];  // A halves: [row][k-pair 0..7]
    __shared__ uint32_t Bs2[64][AP2];   // B halves: [col][k-pair 0..7]
    const int tid    = threadIdx.x;
    const int lane   = tid & 31;
    const int wid    = tid >> 5;
    const int warp_m = (wid & 3) * 32;   // 4 warps along M
    const int warp_n = (wid >> 2) * 32;  // 2 warps along N (CTA covers 64)
    const int brow   = blockIdx.x * 128;
    const int bcol   = blockIdx.y * 64;

    float acc[2][4][4];
    #pragma unroll
    for (int mt = 0; mt < 2; mt++)
        #pragma unroll
        for (int nt = 0; nt < 4; nt++)
            #pragma unroll
            for (int q = 0; q < 4; q++) acc[mt][nt][q] = 0.f;

    const int a_row = tid >> 1;          // 0..127
    const int a_kq  = (tid & 1) * 4;     // uint index 0 or 4
    const int b_nn  = tid >> 2;          // 0..63
    const int b_kk  = (tid & 3) * 2;     // uint index 0,2,4,6

    // ldmatrix source addresses (fixed per lane)
    uint32_t addrA[2], addrB[2];
    #pragma unroll
    for (int mt = 0; mt < 2; mt++) {
        int row = warp_m + mt * 16 + (lane & 15);
        int c   = (lane >> 4) * 4;
        addrA[mt] = (uint32_t)__cvta_generic_to_shared(&As2[row][c]);
    }
    #pragma unroll
    for (int nt2 = 0; nt2 < 2; nt2++) {
        int col = warp_n + nt2 * 16 + ((lane >> 4) & 1) * 8 + (lane & 7);
        int c   = ((lane >> 3) & 1) * 4;
        addrB[nt2] = (uint32_t)__cvta_generic_to_shared(&Bs2[col][c]);
    }

    for (int k0 = 0; k0 < NFEAT; k0 += 16) {
        // stage A: 8 fp32 -> 4 packed half2 per thread
        int gr = brow + a_row;
        float4 v0 = make_float4(0.f, 0.f, 0.f, 0.f);
        float4 v1 = make_float4(0.f, 0.f, 0.f, 0.f);
        if (gr < M) {
            v0 = *reinterpret_cast<const float4*>(&A[(long long)gr * NFEAT + k0 + a_kq * 2]);
            v1 = *reinterpret_cast<const float4*>(&A[(long long)gr * NFEAT + k0 + a_kq * 2 + 4]);
        }
        uint4 au;
        au.x = pack_h2(v0.x, v0.y);
        au.y = pack_h2(v0.z, v0.w);
        au.z = pack_h2(v1.x, v1.y);
        au.w = pack_h2(v1.z, v1.w);
        *reinterpret_cast<uint4*>(&As2[a_row][a_kq]) = au;

        // stage B: Bs2[nn][u] = (W1[k0+2u][bcol+nn], W1[k0+2u+1][bcol+nn])
        {
            int nng = bcol + b_nn;
            float f0 = B[(k0 + 2 * b_kk + 0) * NHID + nng];
            float f1 = B[(k0 + 2 * b_kk + 1) * NHID + nng];
            float f2 = B[(k0 + 2 * b_kk + 2) * NHID + nng];
            float f3 = B[(k0 + 2 * b_kk + 3) * NHID + nng];
            Bs2[b_nn][b_kk]     = pack_h2(f0, f1);
            Bs2[b_nn][b_kk + 1] = pack_h2(f2, f3);
        }
        __syncthreads();

        uint32_t afr[2][4], bfr[2][4];
        ldmat4(afr[0], addrA[0]);
        ldmat4(afr[1], addrA[1]);
        ldmat4(bfr[0], addrB[0]);
        ldmat4(bfr[1], addrB[1]);
        #pragma unroll
        for (int nt = 0; nt < 4; nt++) {
            uint32_t b0 = bfr[nt >> 1][(nt & 1) * 2];
            uint32_t b1 = bfr[nt >> 1][(nt & 1) * 2 + 1];
            mma_f16(acc[0][nt], afr[0], b0, b1);
            mma_f16(acc[1][nt], afr[1], b0, b1);
        }
        __syncthreads();
    }

    // epilogue: write h1 as fp16
    const int r4 = lane >> 2;
    const int c4 = lane & 3;
    #pragma unroll
    for (int mt = 0; mt < 2; mt++) {
        int row0 = brow + warp_m + mt * 16 + r4;
        #pragma unroll
        for (int nt = 0; nt < 4; nt++) {
            int col = bcol + warp_n + nt * 8 + 2 * c4;
            if (row0 < M)
                *reinterpret_cast<__half2*>(&g_h1h[(long long)row0 * NHID + col]) =
                    __floats2half2_rn(acc[mt][nt][0], acc[mt][nt][1]);
            if (row0 + 8 < M)
                *reinterpret_cast<__half2*>(&g_h1h[(long long)(row0 + 8) * NHID + col]) =
                    __floats2half2_rn(acc[mt][nt][2], acc[mt][nt][3]);
        }
    }
}

// ---------------- agg1: g1 = relu(Ahat @ h1 + b1), warp per node, fp16 gather
__global__ void __launch_bounds__(256) k_agg1(const float* __restrict__ b1, int n) {
    int gtid = blockIdx.x * blockDim.x + threadIdx.x;
    int node = gtid >> 5;
    int lane = threadIdx.x & 31;
    if (node >= n) return;
    const uint2* h1v = reinterpret_cast<const uint2*>(g_h1h); // 8B = 4 halves per lane
    float dv = g_dinv[node];
    float sw = dv * dv;

    uint2 hu = h1v[(long long)node * 32 + lane];
    float2 p0 = __half22float2(*reinterpret_cast<__half2*>(&hu.x));
    float2 p1 = __half22float2(*reinterpret_cast<__half2*>(&hu.y));
    float ax = p0.x * sw, ay = p0.y * sw, az = p1.x * sw, aw = p1.y * sw;

    int p = g_off[node], end = g_off[node + 1];
    for (; p + 3 < end; p += 4) {
        int2 e0 = g_edge[p],     e1 = g_edge[p + 1];
        int2 e2 = g_edge[p + 2], e3 = g_edge[p + 3];
        float w0 = __int_as_float(e0.y), w1 = __int_as_float(e1.y);
        float w2 = __int_as_float(e2.y), w3 = __int_as_float(e3.y);
        uint2 u0 = h1v[(long long)e0.x * 32 + lane];
        uint2 u1 = h1v[(long long)e1.x * 32 + lane];
        uint2 u2 = h1v[(long long)e2.x * 32 + lane];
        uint2 u3 = h1v[(long long)e3.x * 32 + lane];
        float2 a0 = __half22float2(*reinterpret_cast<__half2*>(&u0.x));
        float2 c0 = __half22float2(*reinterpret_cast<__half2*>(&u0.y));
        float2 a1 = __half22float2(*reinterpret_cast<__half2*>(&u1.x));
        float2 c1 = __half22float2(*reinterpret_cast<__half2*>(&u1.y));
        float2 a2 = __half22float2(*reinterpret_cast<__half2*>(&u2.x));
        float2 c2 = __half22float2(*reinterpret_cast<__half2*>(&u2.y));
        float2 a3 = __half22float2(*reinterpret_cast<__half2*>(&u3.x));
        float2 c3 = __half22float2(*reinterpret_cast<__half2*>(&u3.y));
        ax += a0.x * w0 + a1.x * w1 + a2.x * w2 + a3.x * w3;
        ay += a0.y * w0 + a1.y * w1 + a2.y * w2 + a3.y * w3;
        az += c0.x * w0 + c1.x * w1 + c2.x * w2 + c3.x * w3;
        aw += c0.y * w0 + c1.y * w1 + c2.y * w2 + c3.y * w3;
    }
    for (; p < end; p++) {
        int2 e0 = g_edge[p];
        float w0 = __int_as_float(e0.y);
        uint2 u0 = h1v[(long long)e0.x * 32 + lane];
        float2 a0 = __half22float2(*reinterpret_cast<__half2*>(&u0.x));
        float2 c0 = __half22float2(*reinterpret_cast<__half2*>(&u0.y));
        ax += a0.x * w0; ay += a0.y * w0; az += c0.x * w0; aw += c0.y * w0;
    }
    float4 bb = reinterpret_cast<const float4*>(b1)[lane];
    float4 out;
    out.x = fmaxf(ax + bb.x, 0.f);
    out.y = fmaxf(ay + bb.y, 0.f);
    out.z = fmaxf(az + bb.z, 0.f);
    out.w = fmaxf(aw + bb.w, 0.f);
    reinterpret_cast<float4*>(g_g1)[(long long)node * 32 + lane] = out;
}

// ---------------- GEMM2: h2 = g1(Mx128) @ W2(128x16), reg-blocked, fp16 out
#define GP 68    // s_g row pad (floats)
#define WP 132   // s_wt row pad (floats)
__global__ void __launch_bounds__(128) k_gemm2(const float* __restrict__ W2, int M) {
    __shared__ float s_g[128][GP];   // [node][k-chunk 64]
    __shared__ float s_wt[16][WP];   // [col][k 0..127] transposed W2
    const int tid  = threadIdx.x;
    const int ng   = tid >> 2;       // node group 0..31 (4 nodes each)
    const int cg   = tid & 3;        // col group 0..3 (4 cols each)
    const int node0 = blockIdx.x * 128;

    for (int idx = tid; idx < 2048; idx += 128) {
        int k = idx >> 4, j = idx & 15;
        s_wt[j][k] = W2[idx];
    }

    float acc[4][4];
    #pragma unroll
    for (int m = 0; m < 4; m++)
        #pragma unroll
        for (int j = 0; j < 4; j++) acc[m][j] = 0.f;

    #pragma unroll
    for (int kc = 0; kc < 2; kc++) {
        const int k0 = kc * 64;
        __syncthreads();
        #pragma unroll
        for (int i = 0; i < 16; i++) {
            int idx = i * 128 + tid;
            int nd = idx >> 4, kq = idx & 15;
            float4 v = make_float4(0.f, 0.f, 0.f, 0.f);
            if (node0 + nd < M)
                v = *reinterpret_cast<const float4*>(&g_g1[(long long)(node0 + nd) * NHID + k0 + kq * 4]);
            *reinterpret_cast<float4*>(&s_g[nd][kq * 4]) = v;
        }
        __syncthreads();
        #pragma unroll
        for (int kq = 0; kq < 16; kq++) {
            float4 a[4], b[4];
            #pragma unroll
            for (int m = 0; m < 4; m++)
                a[m] = *reinterpret_cast<const float4*>(&s_g[ng * 4 + m][kq * 4]);
            #pragma unroll
            for (int j = 0; j < 4; j++)
                b[j] = *reinterpret_cast<const float4*>(&s_wt[cg * 4 + j][k0 + kq * 4]);
            #pragma unroll
            for (int m = 0; m < 4; m++)
                #pragma unroll
                for (int j = 0; j < 4; j++)
                    acc[m][j] += a[m].x * b[j].x + a[m].y * b[j].y
                               + a[m].z * b[j].z + a[m].w * b[j].w;
        }
    }

    #pragma unroll
    for (int m = 0; m < 4; m++) {
        int nd = node0 + ng * 4 + m;
        if (nd < M) {
            __half2 q0 = __floats2half2_rn(acc[m][0], acc[m][1]);
            __half2 q1 = __floats2half2_rn(acc[m][2], acc[m][3]);
            *reinterpret_cast<__half2*>(&g_h2h[(long long)nd * 16 + cg * 4])     = q0;
            *reinterpret_cast<__half2*>(&g_h2h[(long long)nd * 16 + cg * 4 + 2]) = q1;
        }
    }
}

// ---------------- agg2: out = Ahat @ h2 + b2, 16 threads per node, fp16 ----
__global__ void __launch_bounds__(256) k_agg2(const float* __restrict__ b2,
                                              float* __restrict__ out, int n) {
    int gtid = blockIdx.x * blockDim.x + threadIdx.x;
    int node = gtid >> 4;
    int lane = threadIdx.x & 15;
    if (node >= n) return;
    float dv = g_dinv[node];
    float acc = __half2float(g_h2h[(long long)node * 16 + lane]) * dv * dv;
    int p = g_off[node], end = g_off[node + 1];
    for (; p + 3 < end; p += 4) {
        int2 e0 = g_edge[p],     e1 = g_edge[p + 1];
        int2 e2 = g_edge[p + 2], e3 = g_edge[p + 3];
        acc += __half2float(g_h2h[(long long)e0.x * 16 + lane]) * __int_as_float(e0.y)
             + __half2float(g_h2h[(long long)e1.x * 16 + lane]) * __int_as_float(e1.y)
             + __half2float(g_h2h[(long long)e2.x * 16 + lane]) * __int_as_float(e2.y)
             + __half2float(g_h2h[(long long)e3.x * 16 + lane]) * __int_as_float(e3.y);
    }
    for (; p < end; p++) {
        int2 e0 = g_edge[p];
        acc += __half2float(g_h2h[(long long)e0.x * 16 + lane]) * __int_as_float(e0.y);
    }
    out[(long long)node * 16 + lane] = acc + b2[lane];
}

// ---------------- launch ----------------------------------------------------
extern "C" void kernel_launch(void* const* d_in, const int* in_sizes, int n_in,
                              void* d_out, int out_size) {
    const float* x  = (const float*)d_in[0];
    const void*  ei = d_in[1];
    const float* W1 = (const float*)d_in[2];
    const float* b1 = (const float*)d_in[3];
    const float* W2 = (const float*)d_in[4];
    const float* b2 = (const float*)d_in[5];
    float* out = (float*)d_out;

    int n = in_sizes[0] / NFEAT;
    int E = in_sizes[1] / 2;

    int gN = (n + 255) / 256;
    int gE = (E + 255) / 256;
    int nb = (n + SCANB - 1) / SCANB;

    const bool fork = g_hx.ok;
    cudaStream_t sb = fork ? g_hx.s2 : (cudaStream_t)0;

    // fork: graph-build chain runs concurrently with GEMM1.
    // gemm1 stays 4th so ncu's sampled launch profiles it.
    if (fork) {
        cudaEventRecord(g_hx.evA, 0);
        cudaStreamWaitEvent(g_hx.s2, g_hx.evA, 0);
    }
    k_init<<<gN, 256, 0, sb>>>((const int*)ei, n, E);               // 1
    k_count<<<gE, 256, 0, sb>>>(ei, E);                             // 2
    k_scan_block<<<nb, SCANB, 0, sb>>>(n);                          // 3
    k_gemm1<<<dim3((n + 127) / 128, 2), 256>>>(x, W1, n);           // 4 (stream 0)
    k_scan_tops<<<1, 128, 0, sb>>>(nb, n);                          // 5
    k_scan_add<<<nb, SCANB, 0, sb>>>(n);                            // 6
    k_scatter<<<gE, 256, 0, sb>>>(ei, E);                           // 7
    if (fork) {
        cudaEventRecord(g_hx.evB, g_hx.s2);
        cudaStreamWaitEvent(0, g_hx.evB, 0);                        // join
    }
    k_agg1<<<(n * 32 + 255) / 256, 256>>>(b1, n);                   // 8
    k_gemm2<<<(n + 127) / 128, 128>>>(W2, n);                       // 9
    k_agg2<<<(n * 16 + 255) / 256, 256>>>(b2, out, n);              // 10
}

// round 12
// speedup vs baseline: 1.1110x; 1.1059x over previous
#include <cuda_runtime.h>
#include <cuda_fp16.h>
#include <cstdint>

#define NFEAT   256
#define NHID    128
#define NCLS    16
#define MAXN    100000
#define MAXE    1600000
#define SCANB   1024
#define MAXBLK  128

// ---------------- scratch (device globals; no allocation allowed) ----------
__device__ int    g_cnt[MAXN];
__device__ int    g_cur[MAXN];
__device__ int    g_off[MAXN + 1];
__device__ int    g_bsum[MAXBLK];
__device__ int    g_boff[MAXBLK];
__device__ float  g_dinv[MAXN];
__device__ int2   g_edge[MAXE];             // x = src node, y = weight bits
__device__ __half g_h1h[(size_t)MAXN * NHID];   // h1 in fp16 (gather-friendly)
__device__ float  g_g1[(size_t)MAXN * NHID];    // layer-2 input fp32
__device__ __half g_h2h[(size_t)MAXN * NCLS];   // h2 in fp16
__device__ int    g_is64;

// ---------------- static host context: fork-join stream + events -----------
struct HxCtx {
    cudaStream_t s2;
    cudaEvent_t  evA, evB;
    bool ok;
    HxCtx() : ok(false) {
        if (cudaStreamCreateWithFlags(&s2, cudaStreamNonBlocking) != cudaSuccess) return;
        if (cudaEventCreateWithFlags(&evA, cudaEventDisableTiming) != cudaSuccess) return;
        if (cudaEventCreateWithFlags(&evB, cudaEventDisableTiming) != cudaSuccess) return;
        ok = true;
    }
};
static HxCtx g_hx;

// ---------------- index fetch (runtime int32/int64 dispatch) ---------------
__device__ __forceinline__ int edge_idx(const void* ei, long long pos, int is64) {
    if (is64) return (int)((const long long*)ei)[pos];
    return ((const int*)ei)[pos];
}

// ---------------- init: zero counters + detect index dtype -----------------
__global__ void k_init(const int* __restrict__ ei32, int n, int E) {
    int i = blockIdx.x * blockDim.x + threadIdx.x;
    if (i < n) g_cnt[i] = 0;
    if (blockIdx.x == 0) {
        int samples = 4096;
        if (samples > E / 2) samples = E / 2;
        int nz = 0;
        for (int s = threadIdx.x; s < samples; s += blockDim.x)
            if (ei32[2 * s + 1] != 0) nz = 1;
        nz = __syncthreads_or(nz);
        if (threadIdx.x == 0) g_is64 = nz ? 0 : 1;
    }
}

// ---------------- degree count ---------------------------------------------
__global__ void k_count(const void* __restrict__ ei, int E) {
    int e = blockIdx.x * blockDim.x + threadIdx.x;
    if (e >= E) return;
    int c = edge_idx(ei, (long long)E + e, g_is64);
    atomicAdd(&g_cnt[c], 1);
}

// ---------------- scan phase 1: per-block scan + dinv -----------------------
__global__ void __launch_bounds__(SCANB) k_scan_block(int n) {
    __shared__ int warp_sums[32];
    int tid = threadIdx.x, lane = tid & 31, wid = tid >> 5;
    int i = blockIdx.x * SCANB + tid;
    int v = (i < n) ? g_cnt[i] : 0;
    if (i < n) g_dinv[i] = rsqrtf((float)v + 1.0f); // +1 = self loop
    int x = v;
    #pragma unroll
    for (int d = 1; d < 32; d <<= 1) {
        int y = __shfl_up_sync(0xffffffffu, x, d);
        if (lane >= d) x += y;
    }
    if (lane == 31) warp_sums[wid] = x;
    __syncthreads();
    if (wid == 0) {
        int s = warp_sums[lane];
        #pragma unroll
        for (int d = 1; d < 32; d <<= 1) {
            int y = __shfl_up_sync(0xffffffffu, s, d);
            if (lane >= d) s += y;
        }
        warp_sums[lane] = s;
    }
    __syncthreads();
    int excl = x - v + (wid ? warp_sums[wid - 1] : 0);
    if (i < n) g_off[i] = excl;
    if (tid == SCANB - 1) g_bsum[blockIdx.x] = excl + v;
}

// ---------------- scan phase 2 ----------------------------------------------
__global__ void k_scan_tops(int nb, int n) {
    __shared__ int warp_sums[32];
    int tid = threadIdx.x, lane = tid & 31, wid = tid >> 5;
    int v = (tid < nb) ? g_bsum[tid] : 0;
    int x = v;
    #pragma unroll
    for (int d = 1; d < 32; d <<= 1) {
        int y = __shfl_up_sync(0xffffffffu, x, d);
        if (lane >= d) x += y;
    }
    if (lane == 31) warp_sums[wid] = x;
    __syncthreads();
    if (wid == 0) {
        int s = warp_sums[lane];
        #pragma unroll
        for (int d = 1; d < 32; d <<= 1) {
            int y = __shfl_up_sync(0xffffffffu, s, d);
            if (lane >= d) s += y;
        }
        warp_sums[lane] = s;
    }
    __syncthreads();
    int excl = x - v + (wid ? warp_sums[wid - 1] : 0);
    if (tid < nb) g_boff[tid] = excl;
    if (tid == nb - 1) g_off[n] = excl + v;
}

// ---------------- scan phase 3 ----------------------------------------------
__global__ void __launch_bounds__(SCANB) k_scan_add(int n) {
    int i = blockIdx.x * SCANB + threadIdx.x;
    if (i < n) {
        int v = g_off[i] + g_boff[blockIdx.x];
        g_off[i] = v;
        g_cur[i] = v;
    }
}

// ---------------- scatter edges into CSC (interleaved src+w) ---------------
__global__ void k_scatter(const void* __restrict__ ei, int E) {
    int e = blockIdx.x * blockDim.x + threadIdx.x;
    if (e >= E) return;
    int is64 = g_is64;
    int r = edge_idx(ei, e, is64);
    int c = edge_idx(ei, (long long)E + e, is64);
    int p = atomicAdd(&g_cur[c], 1);
    g_edge[p] = make_int2(r, __float_as_int(g_dinv[r] * g_dinv[c]));
}

// ---------------- fp16 mma / ldmatrix helpers -------------------------------
__device__ __forceinline__ void mma_f16(float* d, const uint32_t* a, uint32_t b0, uint32_t b1) {
    asm("mma.sync.aligned.m16n8k16.row.col.f32.f16.f16.f32 "
        "{%0,%1,%2,%3}, {%4,%5,%6,%7}, {%8,%9}, {%0,%1,%2,%3};"
        : "+f"(d[0]), "+f"(d[1]), "+f"(d[2]), "+f"(d[3])
        : "r"(a[0]), "r"(a[1]), "r"(a[2]), "r"(a[3]), "r"(b0), "r"(b1));
}
__device__ __forceinline__ void ldmat4(uint32_t* r, uint32_t addr) {
    asm volatile("ldmatrix.sync.aligned.m8n8.x4.shared.b16 {%0,%1,%2,%3}, [%4];"
        : "=r"(r[0]), "=r"(r[1]), "=r"(r[2]), "=r"(r[3]) : "r"(addr));
}
__device__ __forceinline__ uint32_t pack_h2(float lo, float hi) {
    __half2 h = __floats2half2_rn(lo, hi);
    return *reinterpret_cast<uint32_t*>(&h);
}

// ---------------- GEMM1 (fp16 mma + ldmatrix + reg prefetch) ----------------
// CTA tile 128(M) x 128(N), 8 warps 4(M) x 2(N), warp tile 32x64.
// Gmem chunk k+1 prefetched into registers during chunk k's MMA phase.
#define AP2 12   // padded row length (uints)
__global__ void __launch_bounds__(256, 2) k_gemm1(const float* __restrict__ A,
                                                  const float* __restrict__ B,
                                                  int M) {
    __shared__ uint32_t As2[128][AP2];  // A halves: [row][k-pair 0..7]
    __shared__ uint32_t Bs2[128][AP2];  // B halves: [col][k-pair 0..7]
    const int tid    = threadIdx.x;
    const int lane   = tid & 31;
    const int wid    = tid >> 5;
    const int warp_m = (wid & 3) * 32;   // 4 warps along M
    const int warp_n = (wid >> 2) * 64;  // 2 warps along N
    const int brow   = blockIdx.x * 128;

    float acc[2][8][4];
    #pragma unroll
    for (int mt = 0; mt < 2; mt++)
        #pragma unroll
        for (int nt = 0; nt < 8; nt++)
            #pragma unroll
            for (int q = 0; q < 4; q++) acc[mt][nt][q] = 0.f;

    const int a_row = tid >> 1;          // 0..127
    const int a_kq  = (tid & 1) * 4;     // uint index 0 or 4
    const int b_nn  = tid >> 1;          // 0..127
    const int b_kq  = (tid & 1) * 4;     // uint index 0 or 4

    // ldmatrix source addresses (fixed per lane)
    uint32_t addrA[2], addrB[4];
    #pragma unroll
    for (int mt = 0; mt < 2; mt++) {
        int row = warp_m + mt * 16 + (lane & 15);
        int c   = (lane >> 4) * 4;
        addrA[mt] = (uint32_t)__cvta_generic_to_shared(&As2[row][c]);
    }
    #pragma unroll
    for (int i = 0; i < 4; i++) {
        int m = lane >> 3, r = lane & 7;
        int col = warp_n + (2 * i + (m >> 1)) * 8 + r;
        int c   = (m & 1) * 4;
        addrB[i] = (uint32_t)__cvta_generic_to_shared(&Bs2[col][c]);
    }

    // prefetch registers
    float4 av0, av1;
    float  bv[8];
    const int gr = brow + a_row;

    // ---- load chunk 0 ----
    av0 = make_float4(0.f, 0.f, 0.f, 0.f);
    av1 = make_float4(0.f, 0.f, 0.f, 0.f);
    if (gr < M) {
        av0 = *reinterpret_cast<const float4*>(&A[(long long)gr * NFEAT + a_kq * 2]);
        av1 = *reinterpret_cast<const float4*>(&A[(long long)gr * NFEAT + a_kq * 2 + 4]);
    }
    #pragma unroll
    for (int j = 0; j < 4; j++) {
        bv[2 * j]     = B[(2 * (b_kq + j)) * NHID + b_nn];
        bv[2 * j + 1] = B[(2 * (b_kq + j) + 1) * NHID + b_nn];
    }

    for (int k0 = 0; k0 < NFEAT; k0 += 16) {
        // store prefetched chunk to smem
        uint4 au;
        au.x = pack_h2(av0.x, av0.y);
        au.y = pack_h2(av0.z, av0.w);
        au.z = pack_h2(av1.x, av1.y);
        au.w = pack_h2(av1.z, av1.w);
        *reinterpret_cast<uint4*>(&As2[a_row][a_kq]) = au;
        uint4 bu;
        bu.x = pack_h2(bv[0], bv[1]);
        bu.y = pack_h2(bv[2], bv[3]);
        bu.z = pack_h2(bv[4], bv[5]);
        bu.w = pack_h2(bv[6], bv[7]);
        *reinterpret_cast<uint4*>(&Bs2[b_nn][b_kq]) = bu;
        __syncthreads();

        // issue gmem loads for next chunk (latency hidden under MMA phase)
        const int k1 = k0 + 16;
        if (k1 < NFEAT) {
            av0 = make_float4(0.f, 0.f, 0.f, 0.f);
            av1 = make_float4(0.f, 0.f, 0.f, 0.f);
            if (gr < M) {
                av0 = *reinterpret_cast<const float4*>(&A[(long long)gr * NFEAT + k1 + a_kq * 2]);
                av1 = *reinterpret_cast<const float4*>(&A[(long long)gr * NFEAT + k1 + a_kq * 2 + 4]);
            }
            #pragma unroll
            for (int j = 0; j < 4; j++) {
                bv[2 * j]     = B[(k1 + 2 * (b_kq + j)) * NHID + b_nn];
                bv[2 * j + 1] = B[(k1 + 2 * (b_kq + j) + 1) * NHID + b_nn];
            }
        }

        // fragments + MMA
        uint32_t afr[2][4], bfr[4][4];
        ldmat4(afr[0], addrA[0]);
        ldmat4(afr[1], addrA[1]);
        ldmat4(bfr[0], addrB[0]);
        ldmat4(bfr[1], addrB[1]);
        ldmat4(bfr[2], addrB[2]);
        ldmat4(bfr[3], addrB[3]);
        #pragma unroll
        for (int nt = 0; nt < 8; nt++) {
            uint32_t b0 = bfr[nt >> 1][(nt & 1) * 2];
            uint32_t b1 = bfr[nt >> 1][(nt & 1) * 2 + 1];
            mma_f16(acc[0][nt], afr[0], b0, b1);
            mma_f16(acc[1][nt], afr[1], b0, b1);
        }
        __syncthreads();
    }

    // epilogue: write h1 as fp16
    const int r4 = lane >> 2;
    const int c4 = lane & 3;
    #pragma unroll
    for (int mt = 0; mt < 2; mt++) {
        int row0 = brow + warp_m + mt * 16 + r4;
        #pragma unroll
        for (int nt = 0; nt < 8; nt++) {
            int col = warp_n + nt * 8 + 2 * c4;
            if (row0 < M)
                *reinterpret_cast<__half2*>(&g_h1h[(long long)row0 * NHID + col]) =
                    __floats2half2_rn(acc[mt][nt][0], acc[mt][nt][1]);
            if (row0 + 8 < M)
                *reinterpret_cast<__half2*>(&g_h1h[(long long)(row0 + 8) * NHID + col]) =
                    __floats2half2_rn(acc[mt][nt][2], acc[mt][nt][3]);
        }
    }
}

// ---------------- agg1: g1 = relu(Ahat @ h1 + b1), warp per node, fp16 gather
__global__ void __launch_bounds__(256) k_agg1(const float* __restrict__ b1, int n) {
    int gtid = blockIdx.x * blockDim.x + threadIdx.x;
    int node = gtid >> 5;
    int lane = threadIdx.x & 31;
    if (node >= n) return;
    const uint2* h1v = reinterpret_cast<const uint2*>(g_h1h); // 8B = 4 halves per lane
    float dv = g_dinv[node];
    float sw = dv * dv;

    uint2 hu = h1v[(long long)node * 32 + lane];
    float2 p0 = __half22float2(*reinterpret_cast<__half2*>(&hu.x));
    float2 p1 = __half22float2(*reinterpret_cast<__half2*>(&hu.y));
    float ax = p0.x * sw, ay = p0.y * sw, az = p1.x * sw, aw = p1.y * sw;

    int p = g_off[node], end = g_off[node + 1];
    for (; p + 3 < end; p += 4) {
        int2 e0 = g_edge[p],     e1 = g_edge[p + 1];
        int2 e2 = g_edge[p + 2], e3 = g_edge[p + 3];
        float w0 = __int_as_float(e0.y), w1 = __int_as_float(e1.y);
        float w2 = __int_as_float(e2.y), w3 = __int_as_float(e3.y);
        uint2 u0 = h1v[(long long)e0.x * 32 + lane];
        uint2 u1 = h1v[(long long)e1.x * 32 + lane];
        uint2 u2 = h1v[(long long)e2.x * 32 + lane];
        uint2 u3 = h1v[(long long)e3.x * 32 + lane];
        float2 a0 = __half22float2(*reinterpret_cast<__half2*>(&u0.x));
        float2 c0 = __half22float2(*reinterpret_cast<__half2*>(&u0.y));
        float2 a1 = __half22float2(*reinterpret_cast<__half2*>(&u1.x));
        float2 c1 = __half22float2(*reinterpret_cast<__half2*>(&u1.y));
        float2 a2 = __half22float2(*reinterpret_cast<__half2*>(&u2.x));
        float2 c2 = __half22float2(*reinterpret_cast<__half2*>(&u2.y));
        float2 a3 = __half22float2(*reinterpret_cast<__half2*>(&u3.x));
        float2 c3 = __half22float2(*reinterpret_cast<__half2*>(&u3.y));
        ax += a0.x * w0 + a1.x * w1 + a2.x * w2 + a3.x * w3;
        ay += a0.y * w0 + a1.y * w1 + a2.y * w2 + a3.y * w3;
        az += c0.x * w0 + c1.x * w1 + c2.x * w2 + c3.x * w3;
        aw += c0.y * w0 + c1.y * w1 + c2.y * w2 + c3.y * w3;
    }
    for (; p < end; p++) {
        int2 e0 = g_edge[p];
        float w0 = __int_as_float(e0.y);
        uint2 u0 = h1v[(long long)e0.x * 32 + lane];
        float2 a0 = __half22float2(*reinterpret_cast<__half2*>(&u0.x));
        float2 c0 = __half22float2(*reinterpret_cast<__half2*>(&u0.y));
        ax += a0.x * w0; ay += a0.y * w0; az += c0.x * w0; aw += c0.y * w0;
    }
    float4 bb = reinterpret_cast<const float4*>(b1)[lane];
    float4 out;
    out.x = fmaxf(ax + bb.x, 0.f);
    out.y = fmaxf(ay + bb.y, 0.f);
    out.z = fmaxf(az + bb.z, 0.f);
    out.w = fmaxf(aw + bb.w, 0.f);
    reinterpret_cast<float4*>(g_g1)[(long long)node * 32 + lane] = out;
}

// ---------------- GEMM2: h2 = g1(Mx128) @ W2(128x16), reg-blocked, fp16 out
#define GP 68    // s_g row pad (floats)
#define WP 132   // s_wt row pad (floats)
__global__ void __launch_bounds__(128) k_gemm2(const float* __restrict__ W2, int M) {
    __shared__ float s_g[128][GP];   // [node][k-chunk 64]
    __shared__ float s_wt[16][WP];   // [col][k 0..127] transposed W2
    const int tid  = threadIdx.x;
    const int ng   = tid >> 2;       // node group 0..31 (4 nodes each)
    const int cg   = tid & 3;        // col group 0..3 (4 cols each)
    const int node0 = blockIdx.x * 128;

    for (int idx = tid; idx < 2048; idx += 128) {
        int k = idx >> 4, j = idx & 15;
        s_wt[j][k] = W2[idx];
    }

    float acc[4][4];
    #pragma unroll
    for (int m = 0; m < 4; m++)
        #pragma unroll
        for (int j = 0; j < 4; j++) acc[m][j] = 0.f;

    #pragma unroll
    for (int kc = 0; kc < 2; kc++) {
        const int k0 = kc * 64;
        __syncthreads();
        #pragma unroll
        for (int i = 0; i < 16; i++) {
            int idx = i * 128 + tid;
            int nd = idx >> 4, kq = idx & 15;
            float4 v = make_float4(0.f, 0.f, 0.f, 0.f);
            if (node0 + nd < M)
                v = *reinterpret_cast<const float4*>(&g_g1[(long long)(node0 + nd) * NHID + k0 + kq * 4]);
            *reinterpret_cast<float4*>(&s_g[nd][kq * 4]) = v;
        }
        __syncthreads();
        #pragma unroll
        for (int kq = 0; kq < 16; kq++) {
            float4 a[4], b[4];
            #pragma unroll
            for (int m = 0; m < 4; m++)
                a[m] = *reinterpret_cast<const float4*>(&s_g[ng * 4 + m][kq * 4]);
            #pragma unroll
            for (int j = 0; j < 4; j++)
                b[j] = *reinterpret_cast<const float4*>(&s_wt[cg * 4 + j][k0 + kq * 4]);
            #pragma unroll
            for (int m = 0; m < 4; m++)
                #pragma unroll
                for (int j = 0; j < 4; j++)
                    acc[m][j] += a[m].x * b[j].x + a[m].y * b[j].y
                               + a[m].z * b[j].z + a[m].w * b[j].w;
        }
    }

    #pragma unroll
    for (int m = 0; m < 4; m++) {
        int nd = node0 + ng * 4 + m;
        if (nd < M) {
            __half2 q0 = __floats2half2_rn(acc[m][0], acc[m][1]);
            __half2 q1 = __floats2half2_rn(acc[m][2], acc[m][3]);
            *reinterpret_cast<__half2*>(&g_h2h[(long long)nd * 16 + cg * 4])     = q0;
            *reinterpret_cast<__half2*>(&g_h2h[(long long)nd * 16 + cg * 4 + 2]) = q1;
        }
    }
}

// ---------------- agg2: out = Ahat @ h2 + b2, 16 threads per node, fp16 ----
__global__ void __launch_bounds__(256) k_agg2(const float* __restrict__ b2,
                                              float* __restrict__ out, int n) {
    int gtid = blockIdx.x * blockDim.x + threadIdx.x;
    int node = gtid >> 4;
    int lane = threadIdx.x & 15;
    if (node >= n) return;
    float dv = g_dinv[node];
    float acc = __half2float(g_h2h[(long long)node * 16 + lane]) * dv * dv;
    int p = g_off[node], end = g_off[node + 1];
    for (; p + 3 < end; p += 4) {
        int2 e0 = g_edge[p],     e1 = g_edge[p + 1];
        int2 e2 = g_edge[p + 2], e3 = g_edge[p + 3];
        acc += __half2float(g_h2h[(long long)e0.x * 16 + lane]) * __int_as_float(e0.y)
             + __half2float(g_h2h[(long long)e1.x * 16 + lane]) * __int_as_float(e1.y)
             + __half2float(g_h2h[(long long)e2.x * 16 + lane]) * __int_as_float(e2.y)
             + __half2float(g_h2h[(long long)e3.x * 16 + lane]) * __int_as_float(e3.y);
    }
    for (; p < end; p++) {
        int2 e0 = g_edge[p];
        acc += __half2float(g_h2h[(long long)e0.x * 16 + lane]) * __int_as_float(e0.y);
    }
    out[(long long)node * 16 + lane] = acc + b2[lane];
}

// ---------------- launch ----------------------------------------------------
extern "C" void kernel_launch(void* const* d_in, const int* in_sizes, int n_in,
                              void* d_out, int out_size) {
    const float* x  = (const float*)d_in[0];
    const void*  ei = d_in[1];
    const float* W1 = (const float*)d_in[2];
    const float* b1 = (const float*)d_in[3];
    const float* W2 = (const float*)d_in[4];
    const float* b2 = (const float*)d_in[5];
    float* out = (float*)d_out;

    int n = in_sizes[0] / NFEAT;
    int E = in_sizes[1] / 2;

    int gN = (n + 255) / 256;
    int gE = (E + 255) / 256;
    int nb = (n + SCANB - 1) / SCANB;

    const bool fork = g_hx.ok;
    cudaStream_t sb = fork ? g_hx.s2 : (cudaStream_t)0;

    // fork: graph-build chain runs concurrently with GEMM1.
    // gemm1 stays 4th so ncu's sampled launch profiles it.
    if (fork) {
        cudaEventRecord(g_hx.evA, 0);
        cudaStreamWaitEvent(g_hx.s2, g_hx.evA, 0);
    }
    k_init<<<gN, 256, 0, sb>>>((const int*)ei, n, E);               // 1
    k_count<<<gE, 256, 0, sb>>>(ei, E);                             // 2
    k_scan_block<<<nb, SCANB, 0, sb>>>(n);                          // 3
    k_gemm1<<<(n + 127) / 128, 256>>>(x, W1, n);                    // 4 (stream 0)
    k_scan_tops<<<1, 128, 0, sb>>>(nb, n);                          // 5
    k_scan_add<<<nb, SCANB, 0, sb>>>(n);                            // 6
    k_scatter<<<gE, 256, 0, sb>>>(ei, E);                           // 7
    if (fork) {
        cudaEventRecord(g_hx.evB, g_hx.s2);
        cudaStreamWaitEvent(0, g_hx.evB, 0);                        // join
    }
    k_agg1<<<(n * 32 + 255) / 256, 256>>>(b1, n);                   // 8
    k_gemm2<<<(n + 127) / 128, 128>>>(W2, n);                       // 9
    k_agg2<<<(n * 16 + 255) / 256, 256>>>(b2, out, n);              // 10
}

// round 13
// speedup vs baseline: 1.1320x; 1.0189x over previous
#include <cuda_runtime.h>
#include <cuda_fp16.h>
#include <cstdint>

#define NFEAT   256
#define NHID    128
#define NCLS    16
#define MAXN    100000
#define MAXE    1600000
#define SCANB   1024
#define MAXBLK  128

// ---------------- scratch (device globals; no allocation allowed) ----------
__device__ int    g_cnt[MAXN];
__device__ int    g_cur[MAXN];
__device__ int    g_off[MAXN + 1];
__device__ int    g_bsum[MAXBLK];
__device__ int    g_boff[MAXBLK];
__device__ float  g_dinv[MAXN];
__device__ int2   g_edge[MAXE];             // x = src node, y = weight bits
__device__ uint32_t g_w1p[NHID * (NFEAT / 2)]; // W1 fp16, [n][k-pair] packed
__device__ __half g_h1h[(size_t)MAXN * NHID];   // h1 in fp16 (gather-friendly)
__device__ float  g_g1[(size_t)MAXN * NHID];    // layer-2 input fp32
__device__ __half g_h2h[(size_t)MAXN * NCLS];   // h2 in fp16
__device__ int    g_is64;

// ---------------- static host context: fork-join stream + events -----------
struct HxCtx {
    cudaStream_t s2;
    cudaEvent_t  evA, evB;
    bool ok;
    HxCtx() : ok(false) {
        if (cudaStreamCreateWithFlags(&s2, cudaStreamNonBlocking) != cudaSuccess) return;
        if (cudaEventCreateWithFlags(&evA, cudaEventDisableTiming) != cudaSuccess) return;
        if (cudaEventCreateWithFlags(&evB, cudaEventDisableTiming) != cudaSuccess) return;
        ok = true;
    }
};
static HxCtx g_hx;

// ---------------- index fetch (runtime int32/int64 dispatch) ---------------
__device__ __forceinline__ int edge_idx(const void* ei, long long pos, int is64) {
    if (is64) return (int)((const long long*)ei)[pos];
    return ((const int*)ei)[pos];
}

// ---------------- init: zero counters + detect index dtype -----------------
__global__ void k_init(const int* __restrict__ ei32, int n, int E) {
    int i = blockIdx.x * blockDim.x + threadIdx.x;
    if (i < n) g_cnt[i] = 0;
    if (blockIdx.x == 0) {
        int samples = 4096;
        if (samples > E / 2) samples = E / 2;
        int nz = 0;
        for (int s = threadIdx.x; s < samples; s += blockDim.x)
            if (ei32[2 * s + 1] != 0) nz = 1;
        nz = __syncthreads_or(nz);
        if (threadIdx.x == 0) g_is64 = nz ? 0 : 1;
    }
}

// ---------------- degree count ---------------------------------------------
__global__ void k_count(const void* __restrict__ ei, int E) {
    int e = blockIdx.x * blockDim.x + threadIdx.x;
    if (e >= E) return;
    int c = edge_idx(ei, (long long)E + e, g_is64);
    atomicAdd(&g_cnt[c], 1);
}

// ---------------- scan phase 1: per-block scan + dinv -----------------------
__global__ void __launch_bounds__(SCANB) k_scan_block(int n) {
    __shared__ int warp_sums[32];
    int tid = threadIdx.x, lane = tid & 31, wid = tid >> 5;
    int i = blockIdx.x * SCANB + tid;
    int v = (i < n) ? g_cnt[i] : 0;
    if (i < n) g_dinv[i] = rsqrtf((float)v + 1.0f); // +1 = self loop
    int x = v;
    #pragma unroll
    for (int d = 1; d < 32; d <<= 1) {
        int y = __shfl_up_sync(0xffffffffu, x, d);
        if (lane >= d) x += y;
    }
    if (lane == 31) warp_sums[wid] = x;
    __syncthreads();
    if (wid == 0) {
        int s = warp_sums[lane];
        #pragma unroll
        for (int d = 1; d < 32; d <<= 1) {
            int y = __shfl_up_sync(0xffffffffu, s, d);
            if (lane >= d) s += y;
        }
        warp_sums[lane] = s;
    }
    __syncthreads();
    int excl = x - v + (wid ? warp_sums[wid - 1] : 0);
    if (i < n) g_off[i] = excl;
    if (tid == SCANB - 1) g_bsum[blockIdx.x] = excl + v;
}

// ---------------- scan phase 2 ----------------------------------------------
__global__ void k_scan_tops(int nb, int n) {
    __shared__ int warp_sums[32];
    int tid = threadIdx.x, lane = tid & 31, wid = tid >> 5;
    int v = (tid < nb) ? g_bsum[tid] : 0;
    int x = v;
    #pragma unroll
    for (int d = 1; d < 32; d <<= 1) {
        int y = __shfl_up_sync(0xffffffffu, x, d);
        if (lane >= d) x += y;
    }
    if (lane == 31) warp_sums[wid] = x;
    __syncthreads();
    if (wid == 0) {
        int s = warp_sums[lane];
        #pragma unroll
        for (int d = 1; d < 32; d <<= 1) {
            int y = __shfl_up_sync(0xffffffffu, s, d);
            if (lane >= d) s += y;
        }
        warp_sums[lane] = s;
    }
    __syncthreads();
    int excl = x - v + (wid ? warp_sums[wid - 1] : 0);
    if (tid < nb) g_boff[tid] = excl;
    if (tid == nb - 1) g_off[n] = excl + v;
}

// ---------------- scan phase 3 ----------------------------------------------
__global__ void __launch_bounds__(SCANB) k_scan_add(int n) {
    int i = blockIdx.x * SCANB + threadIdx.x;
    if (i < n) {
        int v = g_off[i] + g_boff[blockIdx.x];
        g_off[i] = v;
        g_cur[i] = v;
    }
}

// ---------------- scatter edges into CSC (interleaved src+w) ---------------
__global__ void k_scatter(const void* __restrict__ ei, int E) {
    int e = blockIdx.x * blockDim.x + threadIdx.x;
    if (e >= E) return;
    int is64 = g_is64;
    int r = edge_idx(ei, e, is64);
    int c = edge_idx(ei, (long long)E + e, is64);
    int p = atomicAdd(&g_cur[c], 1);
    g_edge[p] = make_int2(r, __float_as_int(g_dinv[r] * g_dinv[c]));
}

// ---------------- fp16 mma / ldmatrix helpers -------------------------------
__device__ __forceinline__ void mma_f16(float* d, const uint32_t* a, uint32_t b0, uint32_t b1) {
    asm("mma.sync.aligned.m16n8k16.row.col.f32.f16.f16.f32 "
        "{%0,%1,%2,%3}, {%4,%5,%6,%7}, {%8,%9}, {%0,%1,%2,%3};"
        : "+f"(d[0]), "+f"(d[1]), "+f"(d[2]), "+f"(d[3])
        : "r"(a[0]), "r"(a[1]), "r"(a[2]), "r"(a[3]), "r"(b0), "r"(b1));
}
__device__ __forceinline__ void ldmat4(uint32_t* r, uint32_t addr) {
    asm volatile("ldmatrix.sync.aligned.m8n8.x4.shared.b16 {%0,%1,%2,%3}, [%4];"
        : "=r"(r[0]), "=r"(r[1]), "=r"(r[2]), "=r"(r[3]) : "r"(addr));
}
__device__ __forceinline__ uint32_t pack_h2(float lo, float hi) {
    __half2 h = __floats2half2_rn(lo, hi);
    return *reinterpret_cast<uint32_t*>(&h);
}

// ---------------- W1 pre-convert: g_w1p[n][u] = (h(W1[2u][n]), h(W1[2u+1][n]))
__global__ void k_w1h(const float* __restrict__ W1) {
    int idx = blockIdx.x * blockDim.x + threadIdx.x;  // 0..16383
    int nn = idx >> 7, u = idx & 127;
    g_w1p[nn * 128 + u] = pack_h2(W1[(2 * u) * NHID + nn], W1[(2 * u + 1) * NHID + nn]);
}

// ---------------- GEMM1 (fp16 mma + ldmatrix + double-buffered smem) --------
// CTA tile 128(M) x 128(N), 8 warps 4(M) x 2(N), warp tile 32x64.
// One __syncthreads per k-chunk; B staged from pre-packed g_w1p via uint4.
#define AP2 12   // padded row length (uints)
#define BUFB (128 * AP2 * 4)   // bytes per buffer
__global__ void __launch_bounds__(256, 2) k_gemm1(const float* __restrict__ A,
                                                  int M) {
    __shared__ uint32_t As2[2][128][AP2];  // A halves: [buf][row][k-pair]
    __shared__ uint32_t Bs2[2][128][AP2];  // B halves: [buf][col][k-pair]
    const int tid    = threadIdx.x;
    const int lane   = tid & 31;
    const int wid    = tid >> 5;
    const int warp_m = (wid & 3) * 32;   // 4 warps along M
    const int warp_n = (wid >> 2) * 64;  // 2 warps along N
    const int brow   = blockIdx.x * 128;

    float acc[2][8][4];
    #pragma unroll
    for (int mt = 0; mt < 2; mt++)
        #pragma unroll
        for (int nt = 0; nt < 8; nt++)
            #pragma unroll
            for (int q = 0; q < 4; q++) acc[mt][nt][q] = 0.f;

    const int a_row = tid >> 1;          // 0..127
    const int a_kq  = (tid & 1) * 4;     // uint index 0 or 4
    const int b_nn  = tid >> 1;          // 0..127
    const int b_kq  = (tid & 1) * 4;     // uint index 0 or 4

    // ldmatrix source addresses for buffer 0 (buffer 1 = +BUFB)
    uint32_t addrA0[2], addrB0[4];
    #pragma unroll
    for (int mt = 0; mt < 2; mt++) {
        int row = warp_m + mt * 16 + (lane & 15);
        int c   = (lane >> 4) * 4;
        addrA0[mt] = (uint32_t)__cvta_generic_to_shared(&As2[0][row][c]);
    }
    #pragma unroll
    for (int i = 0; i < 4; i++) {
        int m = lane >> 3, r = lane & 7;
        int col = warp_n + (2 * i + (m >> 1)) * 8 + r;
        int c   = (m & 1) * 4;
        addrB0[i] = (uint32_t)__cvta_generic_to_shared(&Bs2[0][col][c]);
    }

    const int gr = brow + a_row;

    // ---- prologue: load + store chunk 0 into buf 0 ----
    {
        float4 av0 = make_float4(0.f, 0.f, 0.f, 0.f);
        float4 av1 = make_float4(0.f, 0.f, 0.f, 0.f);
        if (gr < M) {
            av0 = *reinterpret_cast<const float4*>(&A[(long long)gr * NFEAT + a_kq * 2]);
            av1 = *reinterpret_cast<const float4*>(&A[(long long)gr * NFEAT + a_kq * 2 + 4]);
        }
        uint4 au;
        au.x = pack_h2(av0.x, av0.y);
        au.y = pack_h2(av0.z, av0.w);
        au.z = pack_h2(av1.x, av1.y);
        au.w = pack_h2(av1.z, av1.w);
        *reinterpret_cast<uint4*>(&As2[0][a_row][a_kq]) = au;
        uint4 bu = *reinterpret_cast<const uint4*>(&g_w1p[b_nn * 128 + b_kq]);
        *reinterpret_cast<uint4*>(&Bs2[0][b_nn][b_kq]) = bu;
    }
    __syncthreads();

    #pragma unroll 1
    for (int it = 0; it < 16; it++) {
        const int cur = it & 1;
        const uint32_t boff = cur ? BUFB : 0;

        // prefetch chunk it+1 (gmem loads issue before MMAs consume smem)
        float4 av0, av1;
        uint4  bu;
        const bool more = (it < 15);
        if (more) {
            const int k1 = (it + 1) * 16;
            av0 = make_float4(0.f, 0.f, 0.f, 0.f);
            av1 = make_float4(0.f, 0.f, 0.f, 0.f);
            if (gr < M) {
                av0 = *reinterpret_cast<const float4*>(&A[(long long)gr * NFEAT + k1 + a_kq * 2]);
                av1 = *reinterpret_cast<const float4*>(&A[(long long)gr * NFEAT + k1 + a_kq * 2 + 4]);
            }
            bu = *reinterpret_cast<const uint4*>(&g_w1p[b_nn * 128 + (k1 >> 1) + b_kq]);
        }

        // fragments + MMA from buf[cur]
        uint32_t afr[2][4], bfr[4][4];
        ldmat4(afr[0], addrA0[0] + boff);
        ldmat4(afr[1], addrA0[1] + boff);
        ldmat4(bfr[0], addrB0[0] + boff);
        ldmat4(bfr[1], addrB0[1] + boff);
        ldmat4(bfr[2], addrB0[2] + boff);
        ldmat4(bfr[3], addrB0[3] + boff);
        #pragma unroll
        for (int nt = 0; nt < 8; nt++) {
            uint32_t b0 = bfr[nt >> 1][(nt & 1) * 2];
            uint32_t b1 = bfr[nt >> 1][(nt & 1) * 2 + 1];
            mma_f16(acc[0][nt], afr[0], b0, b1);
            mma_f16(acc[1][nt], afr[1], b0, b1);
        }

        // store prefetched chunk to the other buffer (its readers finished
        // last iteration; the barrier below publishes it for the next one)
        if (more) {
            uint4 au;
            au.x = pack_h2(av0.x, av0.y);
            au.y = pack_h2(av0.z, av0.w);
            au.z = pack_h2(av1.x, av1.y);
            au.w = pack_h2(av1.z, av1.w);
            *reinterpret_cast<uint4*>(&As2[cur ^ 1][a_row][a_kq]) = au;
            *reinterpret_cast<uint4*>(&Bs2[cur ^ 1][b_nn][b_kq]) = bu;
            __syncthreads();
        }
    }

    // epilogue: write h1 as fp16
    const int r4 = lane >> 2;
    const int c4 = lane & 3;
    #pragma unroll
    for (int mt = 0; mt < 2; mt++) {
        int row0 = brow + warp_m + mt * 16 + r4;
        #pragma unroll
        for (int nt = 0; nt < 8; nt++) {
            int col = warp_n + nt * 8 + 2 * c4;
            if (row0 < M)
                *reinterpret_cast<__half2*>(&g_h1h[(long long)row0 * NHID + col]) =
                    __floats2half2_rn(acc[mt][nt][0], acc[mt][nt][1]);
            if (row0 + 8 < M)
                *reinterpret_cast<__half2*>(&g_h1h[(long long)(row0 + 8) * NHID + col]) =
                    __floats2half2_rn(acc[mt][nt][2], acc[mt][nt][3]);
        }
    }
}

// ---------------- agg1: g1 = relu(Ahat @ h1 + b1), warp per node, fp16 gather
__global__ void __launch_bounds__(256) k_agg1(const float* __restrict__ b1, int n) {
    int gtid = blockIdx.x * blockDim.x + threadIdx.x;
    int node = gtid >> 5;
    int lane = threadIdx.x & 31;
    if (node >= n) return;
    const uint2* h1v = reinterpret_cast<const uint2*>(g_h1h); // 8B = 4 halves per lane
    float dv = g_dinv[node];
    float sw = dv * dv;

    uint2 hu = h1v[(long long)node * 32 + lane];
    float2 p0 = __half22float2(*reinterpret_cast<__half2*>(&hu.x));
    float2 p1 = __half22float2(*reinterpret_cast<__half2*>(&hu.y));
    float ax = p0.x * sw, ay = p0.y * sw, az = p1.x * sw, aw = p1.y * sw;

    int p = g_off[node], end = g_off[node + 1];
    for (; p + 3 < end; p += 4) {
        int2 e0 = g_edge[p],     e1 = g_edge[p + 1];
        int2 e2 = g_edge[p + 2], e3 = g_edge[p + 3];
        float w0 = __int_as_float(e0.y), w1 = __int_as_float(e1.y);
        float w2 = __int_as_float(e2.y), w3 = __int_as_float(e3.y);
        uint2 u0 = h1v[(long long)e0.x * 32 + lane];
        uint2 u1 = h1v[(long long)e1.x * 32 + lane];
        uint2 u2 = h1v[(long long)e2.x * 32 + lane];
        uint2 u3 = h1v[(long long)e3.x * 32 + lane];
        float2 a0 = __half22float2(*reinterpret_cast<__half2*>(&u0.x));
        float2 c0 = __half22float2(*reinterpret_cast<__half2*>(&u0.y));
        float2 a1 = __half22float2(*reinterpret_cast<__half2*>(&u1.x));
        float2 c1 = __half22float2(*reinterpret_cast<__half2*>(&u1.y));
        float2 a2 = __half22float2(*reinterpret_cast<__half2*>(&u2.x));
        float2 c2 = __half22float2(*reinterpret_cast<__half2*>(&u2.y));
        float2 a3 = __half22float2(*reinterpret_cast<__half2*>(&u3.x));
        float2 c3 = __half22float2(*reinterpret_cast<__half2*>(&u3.y));
        ax += a0.x * w0 + a1.x * w1 + a2.x * w2 + a3.x * w3;
        ay += a0.y * w0 + a1.y * w1 + a2.y * w2 + a3.y * w3;
        az += c0.x * w0 + c1.x * w1 + c2.x * w2 + c3.x * w3;
        aw += c0.y * w0 + c1.y * w1 + c2.y * w2 + c3.y * w3;
    }
    for (; p < end; p++) {
        int2 e0 = g_edge[p];
        float w0 = __int_as_float(e0.y);
        uint2 u0 = h1v[(long long)e0.x * 32 + lane];
        float2 a0 = __half22float2(*reinterpret_cast<__half2*>(&u0.x));
        float2 c0 = __half22float2(*reinterpret_cast<__half2*>(&u0.y));
        ax += a0.x * w0; ay += a0.y * w0; az += c0.x * w0; aw += c0.y * w0;
    }
    float4 bb = reinterpret_cast<const float4*>(b1)[lane];
    float4 out;
    out.x = fmaxf(ax + bb.x, 0.f);
    out.y = fmaxf(ay + bb.y, 0.f);
    out.z = fmaxf(az + bb.z, 0.f);
    out.w = fmaxf(aw + bb.w, 0.f);
    reinterpret_cast<float4*>(g_g1)[(long long)node * 32 + lane] = out;
}

// ---------------- GEMM2: h2 = g1(Mx128) @ W2(128x16), reg-blocked, fp16 out
#define GP 68    // s_g row pad (floats)
#define WP 132   // s_wt row pad (floats)
__global__ void __launch_bounds__(128) k_gemm2(const float* __restrict__ W2, int M) {
    __shared__ float s_g[128][GP];   // [node][k-chunk 64]
    __shared__ float s_wt[16][WP];   // [col][k 0..127] transposed W2
    const int tid  = threadIdx.x;
    const int ng   = tid >> 2;       // node group 0..31 (4 nodes each)
    const int cg   = tid & 3;        // col group 0..3 (4 cols each)
    const int node0 = blockIdx.x * 128;

    for (int idx = tid; idx < 2048; idx += 128) {
        int k = idx >> 4, j = idx & 15;
        s_wt[j][k] = W2[idx];
    }

    float acc[4][4];
    #pragma unroll
    for (int m = 0; m < 4; m++)
        #pragma unroll
        for (int j = 0; j < 4; j++) acc[m][j] = 0.f;

    #pragma unroll
    for (int kc = 0; kc < 2; kc++) {
        const int k0 = kc * 64;
        __syncthreads();
        #pragma unroll
        for (int i = 0; i < 16; i++) {
            int idx = i * 128 + tid;
            int nd = idx >> 4, kq = idx & 15;
            float4 v = make_float4(0.f, 0.f, 0.f, 0.f);
            if (node0 + nd < M)
                v = *reinterpret_cast<const float4*>(&g_g1[(long long)(node0 + nd) * NHID + k0 + kq * 4]);
            *reinterpret_cast<float4*>(&s_g[nd][kq * 4]) = v;
        }
        __syncthreads();
        #pragma unroll
        for (int kq = 0; kq < 16; kq++) {
            float4 a[4], b[4];
            #pragma unroll
            for (int m = 0; m < 4; m++)
                a[m] = *reinterpret_cast<const float4*>(&s_g[ng * 4 + m][kq * 4]);
            #pragma unroll
            for (int j = 0; j < 4; j++)
                b[j] = *reinterpret_cast<const float4*>(&s_wt[cg * 4 + j][k0 + kq * 4]);
            #pragma unroll
            for (int m = 0; m < 4; m++)
                #pragma unroll
                for (int j = 0; j < 4; j++)
                    acc[m][j] += a[m].x * b[j].x + a[m].y * b[j].y
                               + a[m].z * b[j].z + a[m].w * b[j].w;
        }
    }

    #pragma unroll
    for (int m = 0; m < 4; m++) {
        int nd = node0 + ng * 4 + m;
        if (nd < M) {
            __half2 q0 = __floats2half2_rn(acc[m][0], acc[m][1]);
            __half2 q1 = __floats2half2_rn(acc[m][2], acc[m][3]);
            *reinterpret_cast<__half2*>(&g_h2h[(long long)nd * 16 + cg * 4])     = q0;
            *reinterpret_cast<__half2*>(&g_h2h[(long long)nd * 16 + cg * 4 + 2]) = q1;
        }
    }
}

// ---------------- agg2: out = Ahat @ h2 + b2, 16 threads per node, fp16 ----
__global__ void __launch_bounds__(256) k_agg2(const float* __restrict__ b2,
                                              float* __restrict__ out, int n) {
    int gtid = blockIdx.x * blockDim.x + threadIdx.x;
    int node = gtid >> 4;
    int lane = threadIdx.x & 15;
    if (node >= n) return;
    float dv = g_dinv[node];
    float acc = __half2float(g_h2h[(long long)node * 16 + lane]) * dv * dv;
    int p = g_off[node], end = g_off[node + 1];
    for (; p + 3 < end; p += 4) {
        int2 e0 = g_edge[p],     e1 = g_edge[p + 1];
        int2 e2 = g_edge[p + 2], e3 = g_edge[p + 3];
        acc += __half2float(g_h2h[(long long)e0.x * 16 + lane]) * __int_as_float(e0.y)
             + __half2float(g_h2h[(long long)e1.x * 16 + lane]) * __int_as_float(e1.y)
             + __half2float(g_h2h[(long long)e2.x * 16 + lane]) * __int_as_float(e2.y)
             + __half2float(g_h2h[(long long)e3.x * 16 + lane]) * __int_as_float(e3.y);
    }
    for (; p < end; p++) {
        int2 e0 = g_edge[p];
        acc += __half2float(g_h2h[(long long)e0.x * 16 + lane]) * __int_as_float(e0.y);
    }
    out[(long long)node * 16 + lane] = acc + b2[lane];
}

// ---------------- launch ----------------------------------------------------
extern "C" void kernel_launch(void* const* d_in, const int* in_sizes, int n_in,
                              void* d_out, int out_size) {
    const float* x  = (const float*)d_in[0];
    const void*  ei = d_in[1];
    const float* W1 = (const float*)d_in[2];
    const float* b1 = (const float*)d_in[3];
    const float* W2 = (const float*)d_in[4];
    const float* b2 = (const float*)d_in[5];
    float* out = (float*)d_out;

    int n = in_sizes[0] / NFEAT;
    int E = in_sizes[1] / 2;

    int gN = (n + 255) / 256;
    int gE = (E + 255) / 256;
    int nb = (n + SCANB - 1) / SCANB;

    const bool fork = g_hx.ok;
    cudaStream_t sb = fork ? g_hx.s2 : (cudaStream_t)0;

    // fork: graph-build chain runs concurrently with GEMM1.
    if (fork) {
        cudaEventRecord(g_hx.evA, 0);
        cudaStreamWaitEvent(g_hx.s2, g_hx.evA, 0);
    }
    k_init<<<gN, 256, 0, sb>>>((const int*)ei, n, E);               // 1
    k_count<<<gE, 256, 0, sb>>>(ei, E);                             // 2
    k_scan_block<<<nb, SCANB, 0, sb>>>(n);                          // 3
    k_w1h<<<64, 256>>>(W1);                                         // 4 (stream 0)
    k_gemm1<<<(n + 127) / 128, 256>>>(x, n);                        // 5 (stream 0)
    k_scan_tops<<<1, 128, 0, sb>>>(nb, n);                          // 6
    k_scan_add<<<nb, SCANB, 0, sb>>>(n);                            // 7
    k_scatter<<<gE, 256, 0, sb>>>(ei, E);                           // 8
    if (fork) {
        cudaEventRecord(g_hx.evB, g_hx.s2);
        cudaStreamWaitEvent(0, g_hx.evB, 0);                        // join
    }
    k_agg1<<<(n * 32 + 255) / 256, 256>>>(b1, n);                   // 9
    k_gemm2<<<(n + 127) / 128, 128>>>(W2, n);                       // 10
    k_agg2<<<(n * 16 + 255) / 256, 256>>>(b2, out, n);              // 11
}

// round 14
// speedup vs baseline: 1.2069x; 1.0661x over previous
#include <cuda_runtime.h>
#include <cuda_fp16.h>
#include <cstdint>

#define NFEAT   256
#define NHID    128
#define NCLS    16
#define MAXN    100000
#define MAXE    1600000
#define SCANB   1024
#define MAXBLK  128

// ---------------- scratch (device globals; no allocation allowed) ----------
__device__ int    g_cnt[MAXN];
__device__ int    g_cur[MAXN];
__device__ int    g_off[MAXN + 1];
__device__ int    g_bsum[MAXBLK];
__device__ int    g_boff[MAXBLK];
__device__ float  g_dinv[MAXN];
__device__ int2   g_edge[MAXE];             // x = src node, y = weight bits
__device__ uint32_t g_w1p[NHID * (NFEAT / 2)]; // W1 fp16, [n][k-pair] packed
__device__ __half g_h1h[(size_t)MAXN * NHID];   // h1 in fp16 (gather-friendly)
__device__ uint2  g_g1h[(size_t)MAXN * 32];     // g1 in fp16 (packed 4/lane)
__device__ __half g_h2h[(size_t)MAXN * NCLS];   // h2 in fp16
__device__ int    g_is64;

// ---------------- static host context: fork-join stream + events -----------
struct HxCtx {
    cudaStream_t s2;
    cudaEvent_t  evA, evB;
    bool ok;
    HxCtx() : ok(false) {
        if (cudaStreamCreateWithFlags(&s2, cudaStreamNonBlocking) != cudaSuccess) return;
        if (cudaEventCreateWithFlags(&evA, cudaEventDisableTiming) != cudaSuccess) return;
        if (cudaEventCreateWithFlags(&evB, cudaEventDisableTiming) != cudaSuccess) return;
        ok = true;
    }
};
static HxCtx g_hx;

// ---------------- index fetch (runtime int32/int64 dispatch) ---------------
__device__ __forceinline__ int edge_idx(const void* ei, long long pos, int is64) {
    if (is64) return (int)((const long long*)ei)[pos];
    return ((const int*)ei)[pos];
}

// ---------------- init: zero counters + detect index dtype -----------------
__global__ void k_init(const int* __restrict__ ei32, int n, int E) {
    int i = blockIdx.x * blockDim.x + threadIdx.x;
    if (i < n) g_cnt[i] = 0;
    if (blockIdx.x == 0) {
        int samples = 4096;
        if (samples > E / 2) samples = E / 2;
        int nz = 0;
        for (int s = threadIdx.x; s < samples; s += blockDim.x)
            if (ei32[2 * s + 1] != 0) nz = 1;
        nz = __syncthreads_or(nz);
        if (threadIdx.x == 0) g_is64 = nz ? 0 : 1;
    }
}

// ---------------- degree count ---------------------------------------------
__global__ void k_count(const void* __restrict__ ei, int E) {
    int e = blockIdx.x * blockDim.x + threadIdx.x;
    if (e >= E) return;
    int c = edge_idx(ei, (long long)E + e, g_is64);
    atomicAdd(&g_cnt[c], 1);
}

// ---------------- scan phase 1: per-block scan + dinv -----------------------
__global__ void __launch_bounds__(SCANB) k_scan_block(int n) {
    __shared__ int warp_sums[32];
    int tid = threadIdx.x, lane = tid & 31, wid = tid >> 5;
    int i = blockIdx.x * SCANB + tid;
    int v = (i < n) ? g_cnt[i] : 0;
    if (i < n) g_dinv[i] = rsqrtf((float)v + 1.0f); // +1 = self loop
    int x = v;
    #pragma unroll
    for (int d = 1; d < 32; d <<= 1) {
        int y = __shfl_up_sync(0xffffffffu, x, d);
        if (lane >= d) x += y;
    }
    if (lane == 31) warp_sums[wid] = x;
    __syncthreads();
    if (wid == 0) {
        int s = warp_sums[lane];
        #pragma unroll
        for (int d = 1; d < 32; d <<= 1) {
            int y = __shfl_up_sync(0xffffffffu, s, d);
            if (lane >= d) s += y;
        }
        warp_sums[lane] = s;
    }
    __syncthreads();
    int excl = x - v + (wid ? warp_sums[wid - 1] : 0);
    if (i < n) g_off[i] = excl;
    if (tid == SCANB - 1) g_bsum[blockIdx.x] = excl + v;
}

// ---------------- scan phase 2 ----------------------------------------------
__global__ void k_scan_tops(int nb, int n) {
    __shared__ int warp_sums[32];
    int tid = threadIdx.x, lane = tid & 31, wid = tid >> 5;
    int v = (tid < nb) ? g_bsum[tid] : 0;
    int x = v;
    #pragma unroll
    for (int d = 1; d < 32; d <<= 1) {
        int y = __shfl_up_sync(0xffffffffu, x, d);
        if (lane >= d) x += y;
    }
    if (lane == 31) warp_sums[wid] = x;
    __syncthreads();
    if (wid == 0) {
        int s = warp_sums[lane];
        #pragma unroll
        for (int d = 1; d < 32; d <<= 1) {
            int y = __shfl_up_sync(0xffffffffu, s, d);
            if (lane >= d) s += y;
        }
        warp_sums[lane] = s;
    }
    __syncthreads();
    int excl = x - v + (wid ? warp_sums[wid - 1] : 0);
    if (tid < nb) g_boff[tid] = excl;
    if (tid == nb - 1) g_off[n] = excl + v;
}

// ---------------- scan phase 3 ----------------------------------------------
__global__ void __launch_bounds__(SCANB) k_scan_add(int n) {
    int i = blockIdx.x * SCANB + threadIdx.x;
    if (i < n) {
        int v = g_off[i] + g_boff[blockIdx.x];
        g_off[i] = v;
        g_cur[i] = v;
    }
}

// ---------------- scatter edges into CSC (interleaved src+w) ---------------
__global__ void k_scatter(const void* __restrict__ ei, int E) {
    int e = blockIdx.x * blockDim.x + threadIdx.x;
    if (e >= E) return;
    int is64 = g_is64;
    int r = edge_idx(ei, e, is64);
    int c = edge_idx(ei, (long long)E + e, is64);
    int p = atomicAdd(&g_cur[c], 1);
    g_edge[p] = make_int2(r, __float_as_int(g_dinv[r] * g_dinv[c]));
}

// ---------------- fp16 mma / ldmatrix helpers -------------------------------
__device__ __forceinline__ void mma_f16(float* d, const uint32_t* a, uint32_t b0, uint32_t b1) {
    asm("mma.sync.aligned.m16n8k16.row.col.f32.f16.f16.f32 "
        "{%0,%1,%2,%3}, {%4,%5,%6,%7}, {%8,%9}, {%0,%1,%2,%3};"
        : "+f"(d[0]), "+f"(d[1]), "+f"(d[2]), "+f"(d[3])
        : "r"(a[0]), "r"(a[1]), "r"(a[2]), "r"(a[3]), "r"(b0), "r"(b1));
}
__device__ __forceinline__ void ldmat4(uint32_t* r, uint32_t addr) {
    asm volatile("ldmatrix.sync.aligned.m8n8.x4.shared.b16 {%0,%1,%2,%3}, [%4];"
        : "=r"(r[0]), "=r"(r[1]), "=r"(r[2]), "=r"(r[3]) : "r"(addr));
}
__device__ __forceinline__ uint32_t pack_h2(float lo, float hi) {
    __half2 h = __floats2half2_rn(lo, hi);
    return *reinterpret_cast<uint32_t*>(&h);
}

// ---------------- W1 pre-convert: g_w1p[n][u] = (h(W1[2u][n]), h(W1[2u+1][n]))
__global__ void k_w1h(const float* __restrict__ W1) {
    int idx = blockIdx.x * blockDim.x + threadIdx.x;  // 0..16383
    int nn = idx >> 7, u = idx & 127;
    g_w1p[nn * 128 + u] = pack_h2(W1[(2 * u) * NHID + nn], W1[(2 * u + 1) * NHID + nn]);
}

// ---------------- GEMM1: 512 threads, 16 warps (4x4), warp tile 32x32 -------
#define AP2 12   // padded row length (uints)
#define BUFB (128 * AP2 * 4)   // bytes per buffer
__global__ void __launch_bounds__(512, 2) k_gemm1(const float* __restrict__ A,
                                                  int M) {
    __shared__ uint32_t As2[2][128][AP2];  // A halves: [buf][row][k-pair]
    __shared__ uint32_t Bs2[2][128][AP2];  // B halves: [buf][col][k-pair]
    const int tid    = threadIdx.x;
    const int lane   = tid & 31;
    const int wid    = tid >> 5;          // 0..15
    const int warp_m = (wid & 3) * 32;    // 4 warps along M
    const int warp_n = (wid >> 2) * 32;   // 4 warps along N
    const int brow   = blockIdx.x * 128;

    float acc[2][4][4];
    #pragma unroll
    for (int mt = 0; mt < 2; mt++)
        #pragma unroll
        for (int nt = 0; nt < 4; nt++)
            #pragma unroll
            for (int q = 0; q < 4; q++) acc[mt][nt][q] = 0.f;

    const int a_row = tid >> 2;          // 0..127
    const int a_kq  = (tid & 3) * 2;     // uint index 0,2,4,6
    const int b_nn  = a_row;
    const int b_kq  = a_kq;

    // ldmatrix source addresses for buffer 0 (buffer 1 = +BUFB)
    uint32_t addrA0[2], addrB0[2];
    #pragma unroll
    for (int mt = 0; mt < 2; mt++) {
        int row = warp_m + mt * 16 + (lane & 15);
        int c   = (lane >> 4) * 4;
        addrA0[mt] = (uint32_t)__cvta_generic_to_shared(&As2[0][row][c]);
    }
    #pragma unroll
    for (int i = 0; i < 2; i++) {
        int m = lane >> 3, r = lane & 7;
        int col = warp_n + (2 * i + (m >> 1)) * 8 + r;
        int c   = (m & 1) * 4;
        addrB0[i] = (uint32_t)__cvta_generic_to_shared(&Bs2[0][col][c]);
    }

    const int gr = brow + a_row;

    // ---- prologue: chunk 0 into buf 0 ----
    {
        float4 av = make_float4(0.f, 0.f, 0.f, 0.f);
        if (gr < M)
            av = *reinterpret_cast<const float4*>(&A[(long long)gr * NFEAT + a_kq * 2]);
        uint2 au;
        au.x = pack_h2(av.x, av.y);
        au.y = pack_h2(av.z, av.w);
        *reinterpret_cast<uint2*>(&As2[0][a_row][a_kq]) = au;
        uint2 bu = *reinterpret_cast<const uint2*>(&g_w1p[b_nn * 128 + b_kq]);
        *reinterpret_cast<uint2*>(&Bs2[0][b_nn][b_kq]) = bu;
    }
    __syncthreads();

    #pragma unroll 1
    for (int it = 0; it < 16; it++) {
        const int cur = it & 1;
        const uint32_t boff = cur ? BUFB : 0;

        // prefetch chunk it+1
        float4 av;
        uint2  bu;
        const bool more = (it < 15);
        if (more) {
            const int k1 = (it + 1) * 16;
            av = make_float4(0.f, 0.f, 0.f, 0.f);
            if (gr < M)
                av = *reinterpret_cast<const float4*>(&A[(long long)gr * NFEAT + k1 + a_kq * 2]);
            bu = *reinterpret_cast<const uint2*>(&g_w1p[b_nn * 128 + (k1 >> 1) + b_kq]);
        }

        // fragments + MMA from buf[cur]
        uint32_t afr[2][4], bfr[2][4];
        ldmat4(afr[0], addrA0[0] + boff);
        ldmat4(afr[1], addrA0[1] + boff);
        ldmat4(bfr[0], addrB0[0] + boff);
        ldmat4(bfr[1], addrB0[1] + boff);
        #pragma unroll
        for (int nt = 0; nt < 4; nt++) {
            uint32_t b0 = bfr[nt >> 1][(nt & 1) * 2];
            uint32_t b1 = bfr[nt >> 1][(nt & 1) * 2 + 1];
            mma_f16(acc[0][nt], afr[0], b0, b1);
            mma_f16(acc[1][nt], afr[1], b0, b1);
        }

        // store prefetched chunk to other buffer; barrier publishes it
        if (more) {
            uint2 au;
            au.x = pack_h2(av.x, av.y);
            au.y = pack_h2(av.z, av.w);
            *reinterpret_cast<uint2*>(&As2[cur ^ 1][a_row][a_kq]) = au;
            *reinterpret_cast<uint2*>(&Bs2[cur ^ 1][b_nn][b_kq]) = bu;
            __syncthreads();
        }
    }

    // epilogue: write h1 as fp16
    const int r4 = lane >> 2;
    const int c4 = lane & 3;
    #pragma unroll
    for (int mt = 0; mt < 2; mt++) {
        int row0 = brow + warp_m + mt * 16 + r4;
        #pragma unroll
        for (int nt = 0; nt < 4; nt++) {
            int col = warp_n + nt * 8 + 2 * c4;
            if (row0 < M)
                *reinterpret_cast<__half2*>(&g_h1h[(long long)row0 * NHID + col]) =
                    __floats2half2_rn(acc[mt][nt][0], acc[mt][nt][1]);
            if (row0 + 8 < M)
                *reinterpret_cast<__half2*>(&g_h1h[(long long)(row0 + 8) * NHID + col]) =
                    __floats2half2_rn(acc[mt][nt][2], acc[mt][nt][3]);
        }
    }
}

// ---------------- agg1: g1 = relu(Ahat @ h1 + b1), warp per node, fp16 ------
__global__ void __launch_bounds__(256) k_agg1(const float* __restrict__ b1, int n) {
    int gtid = blockIdx.x * blockDim.x + threadIdx.x;
    int node = gtid >> 5;
    int lane = threadIdx.x & 31;
    if (node >= n) return;
    const uint2* h1v = reinterpret_cast<const uint2*>(g_h1h); // 8B = 4 halves per lane
    float dv = g_dinv[node];
    float sw = dv * dv;

    uint2 hu = h1v[(long long)node * 32 + lane];
    float2 p0 = __half22float2(*reinterpret_cast<__half2*>(&hu.x));
    float2 p1 = __half22float2(*reinterpret_cast<__half2*>(&hu.y));
    float ax = p0.x * sw, ay = p0.y * sw, az = p1.x * sw, aw = p1.y * sw;

    int p = g_off[node], end = g_off[node + 1];
    for (; p + 3 < end; p += 4) {
        int2 e0 = g_edge[p],     e1 = g_edge[p + 1];
        int2 e2 = g_edge[p + 2], e3 = g_edge[p + 3];
        float w0 = __int_as_float(e0.y), w1 = __int_as_float(e1.y);
        float w2 = __int_as_float(e2.y), w3 = __int_as_float(e3.y);
        uint2 u0 = h1v[(long long)e0.x * 32 + lane];
        uint2 u1 = h1v[(long long)e1.x * 32 + lane];
        uint2 u2 = h1v[(long long)e2.x * 32 + lane];
        uint2 u3 = h1v[(long long)e3.x * 32 + lane];
        float2 a0 = __half22float2(*reinterpret_cast<__half2*>(&u0.x));
        float2 c0 = __half22float2(*reinterpret_cast<__half2*>(&u0.y));
        float2 a1 = __half22float2(*reinterpret_cast<__half2*>(&u1.x));
        float2 c1 = __half22float2(*reinterpret_cast<__half2*>(&u1.y));
        float2 a2 = __half22float2(*reinterpret_cast<__half2*>(&u2.x));
        float2 c2 = __half22float2(*reinterpret_cast<__half2*>(&u2.y));
        float2 a3 = __half22float2(*reinterpret_cast<__half2*>(&u3.x));
        float2 c3 = __half22float2(*reinterpret_cast<__half2*>(&u3.y));
        ax += a0.x * w0 + a1.x * w1 + a2.x * w2 + a3.x * w3;
        ay += a0.y * w0 + a1.y * w1 + a2.y * w2 + a3.y * w3;
        az += c0.x * w0 + c1.x * w1 + c2.x * w2 + c3.x * w3;
        aw += c0.y * w0 + c1.y * w1 + c2.y * w2 + c3.y * w3;
    }
    for (; p < end; p++) {
        int2 e0 = g_edge[p];
        float w0 = __int_as_float(e0.y);
        uint2 u0 = h1v[(long long)e0.x * 32 + lane];
        float2 a0 = __half22float2(*reinterpret_cast<__half2*>(&u0.x));
        float2 c0 = __half22float2(*reinterpret_cast<__half2*>(&u0.y));
        ax += a0.x * w0; ay += a0.y * w0; az += c0.x * w0; aw += c0.y * w0;
    }
    float4 bb = reinterpret_cast<const float4*>(b1)[lane];
    uint2 out;
    out.x = pack_h2(fmaxf(ax + bb.x, 0.f), fmaxf(ay + bb.y, 0.f));
    out.y = pack_h2(fmaxf(az + bb.z, 0.f), fmaxf(aw + bb.w, 0.f));
    g_g1h[(long long)node * 32 + lane] = out;
}

// ---------------- GEMM2: h2 = g1(Mx128 fp16) @ W2(128x16), fp16 out ---------
#define GP 68    // s_g row pad (floats)
#define WP 132   // s_wt row pad (floats)
__global__ void __launch_bounds__(128) k_gemm2(const float* __restrict__ W2, int M) {
    __shared__ float s_g[128][GP];   // [node][k-chunk 64] (unpacked fp32)
    __shared__ float s_wt[16][WP];   // [col][k 0..127] transposed W2
    const int tid  = threadIdx.x;
    const int ng   = tid >> 2;       // node group 0..31 (4 nodes each)
    const int cg   = tid & 3;        // col group 0..3 (4 cols each)
    const int node0 = blockIdx.x * 128;

    for (int idx = tid; idx < 2048; idx += 128) {
        int k = idx >> 4, j = idx & 15;
        s_wt[j][k] = W2[idx];
    }

    float acc[4][4];
    #pragma unroll
    for (int m = 0; m < 4; m++)
        #pragma unroll
        for (int j = 0; j < 4; j++) acc[m][j] = 0.f;

    #pragma unroll
    for (int kc = 0; kc < 2; kc++) {
        const int k0 = kc * 64;
        __syncthreads();
        #pragma unroll
        for (int i = 0; i < 16; i++) {
            int idx = i * 128 + tid;
            int nd = idx >> 4, kq = idx & 15;
            float4 v = make_float4(0.f, 0.f, 0.f, 0.f);
            if (node0 + nd < M) {
                uint2 u = g_g1h[(long long)(node0 + nd) * 32 + (k0 >> 2) + kq];
                float2 lo = __half22float2(*reinterpret_cast<__half2*>(&u.x));
                float2 hi = __half22float2(*reinterpret_cast<__half2*>(&u.y));
                v = make_float4(lo.x, lo.y, hi.x, hi.y);
            }
            *reinterpret_cast<float4*>(&s_g[nd][kq * 4]) = v;
        }
        __syncthreads();
        #pragma unroll
        for (int kq = 0; kq < 16; kq++) {
            float4 a[4], b[4];
            #pragma unroll
            for (int m = 0; m < 4; m++)
                a[m] = *reinterpret_cast<const float4*>(&s_g[ng * 4 + m][kq * 4]);
            #pragma unroll
            for (int j = 0; j < 4; j++)
                b[j] = *reinterpret_cast<const float4*>(&s_wt[cg * 4 + j][k0 + kq * 4]);
            #pragma unroll
            for (int m = 0; m < 4; m++)
                #pragma unroll
                for (int j = 0; j < 4; j++)
                    acc[m][j] += a[m].x * b[j].x + a[m].y * b[j].y
                               + a[m].z * b[j].z + a[m].w * b[j].w;
        }
    }

    #pragma unroll
    for (int m = 0; m < 4; m++) {
        int nd = node0 + ng * 4 + m;
        if (nd < M) {
            __half2 q0 = __floats2half2_rn(acc[m][0], acc[m][1]);
            __half2 q1 = __floats2half2_rn(acc[m][2], acc[m][3]);
            *reinterpret_cast<__half2*>(&g_h2h[(long long)nd * 16 + cg * 4])     = q0;
            *reinterpret_cast<__half2*>(&g_h2h[(long long)nd * 16 + cg * 4 + 2]) = q1;
        }
    }
}

// ---------------- agg2: out = Ahat @ h2 + b2, 16 threads per node, fp16 ----
__global__ void __launch_bounds__(256) k_agg2(const float* __restrict__ b2,
                                              float* __restrict__ out, int n) {
    int gtid = blockIdx.x * blockDim.x + threadIdx.x;
    int node = gtid >> 4;
    int lane = threadIdx.x & 15;
    if (node >= n) return;
    float dv = g_dinv[node];
    float acc = __half2float(g_h2h[(long long)node * 16 + lane]) * dv * dv;
    int p = g_off[node], end = g_off[node + 1];
    for (; p + 3 < end; p += 4) {
        int2 e0 = g_edge[p],     e1 = g_edge[p + 1];
        int2 e2 = g_edge[p + 2], e3 = g_edge[p + 3];
        acc += __half2float(g_h2h[(long long)e0.x * 16 + lane]) * __int_as_float(e0.y)
             + __half2float(g_h2h[(long long)e1.x * 16 + lane]) * __int_as_float(e1.y)
             + __half2float(g_h2h[(long long)e2.x * 16 + lane]) * __int_as_float(e2.y)
             + __half2float(g_h2h[(long long)e3.x * 16 + lane]) * __int_as_float(e3.y);
    }
    for (; p < end; p++) {
        int2 e0 = g_edge[p];
        acc += __half2float(g_h2h[(long long)e0.x * 16 + lane]) * __int_as_float(e0.y);
    }
    out[(long long)node * 16 + lane] = acc + b2[lane];
}

// ---------------- launch ----------------------------------------------------
extern "C" void kernel_launch(void* const* d_in, const int* in_sizes, int n_in,
                              void* d_out, int out_size) {
    const float* x  = (const float*)d_in[0];
    const void*  ei = d_in[1];
    const float* W1 = (const float*)d_in[2];
    const float* b1 = (const float*)d_in[3];
    const float* W2 = (const float*)d_in[4];
    const float* b2 = (const float*)d_in[5];
    float* out = (float*)d_out;

    int n = in_sizes[0] / NFEAT;
    int E = in_sizes[1] / 2;

    int gN = (n + 255) / 256;
    int gE = (E + 255) / 256;
    int nb = (n + SCANB - 1) / SCANB;

    const bool fork = g_hx.ok;
    cudaStream_t sb = fork ? g_hx.s2 : (cudaStream_t)0;

    // fork: graph-build chain runs concurrently with GEMM1.
    // gemm1 is 4th host launch so ncu samples it.
    if (fork) {
        cudaEventRecord(g_hx.evA, 0);
        cudaStreamWaitEvent(g_hx.s2, g_hx.evA, 0);
    }
    k_init<<<gN, 256, 0, sb>>>((const int*)ei, n, E);               // 1
    k_count<<<gE, 256, 0, sb>>>(ei, E);                             // 2
    k_w1h<<<64, 256>>>(W1);                                         // 3 (stream 0)
    k_gemm1<<<(n + 127) / 128, 512>>>(x, n);                        // 4 (stream 0)
    k_scan_block<<<nb, SCANB, 0, sb>>>(n);                          // 5
    k_scan_tops<<<1, 128, 0, sb>>>(nb, n);                          // 6
    k_scan_add<<<nb, SCANB, 0, sb>>>(n);                            // 7
    k_scatter<<<gE, 256, 0, sb>>>(ei, E);                           // 8
    if (fork) {
        cudaEventRecord(g_hx.evB, g_hx.s2);
        cudaStreamWaitEvent(0, g_hx.evB, 0);                        // join
    }
    k_agg1<<<(n * 32 + 255) / 256, 256>>>(b1, n);                   // 9
    k_gemm2<<<(n + 127) / 128, 128>>>(W2, n);                       // 10
    k_agg2<<<(n * 16 + 255) / 256, 256>>>(b2, out, n);              // 11
}